// round 9
// baseline (speedup 1.0000x reference)
#include <cuda_runtime.h>
#include <cuda_bf16.h>
#include <math.h>

#define NROWS 2048
#define EMBED 4096
#define SPLITS 16

typedef unsigned long long ull;

__device__ __forceinline__ void ffma2(ull& d, ull a, ull b) {
    asm("fma.rn.f32x2 %0, %1, %2, %3;" : "=l"(d) : "l"(a), "l"(b), "l"(d));
}
__device__ __forceinline__ ull pack2f(float x, float y) {
    ull r; asm("mov.b64 %0, {%1, %2};" : "=l"(r) : "f"(x), "f"(y)); return r;
}
__device__ __forceinline__ float2 unpack2f(ull v) {
    float2 f; asm("mov.b64 {%0, %1}, %2;" : "=f"(f.x), "=f"(f.y) : "l"(v)); return f;
}

// ---------------- scratch ----------------
__device__ float g_part[SPLITS * NROWS * 64];
__device__ float g_XP[NROWS * 256];
__device__ float g_states[NROWS * 192];   // per row: h1[64] c1[64] h2[32] c2[32]
__device__ float g_G[EMBED * 32];
__device__ float g_cvec[EMBED];
__device__ float g_Wcat2[128 * 96];
__device__ float g_b1c[256];
__device__ float g_b2c[128];
__device__ ull g_w1hP[32 * 256];          // k-major packed w1h rows
__device__ ull g_w2P[48 * 128];           // k-major packed [w2i|w2h] rows

__device__ __forceinline__ float sig_f(float x) {
    return __fdividef(1.0f, 1.0f + __expf(-x));
}
__device__ __forceinline__ float tanh_f(float x) {
    return __fdividef(2.0f, 1.0f + __expf(-2.0f * x)) - 1.0f;
}

// ---------------- merged SPP + prep ----------------
__global__ void spp_prep(const float* __restrict__ frames, float* __restrict__ pooled,
                         const float* __restrict__ spp_w, const float* __restrict__ spp_b,
                         const float* __restrict__ fw, const float* __restrict__ fb,
                         const float* __restrict__ b1i, const float* __restrict__ b1h,
                         const float* __restrict__ w1h,
                         const float* __restrict__ w2i, const float* __restrict__ w2h,
                         const float* __restrict__ b2i, const float* __restrict__ b2h) {
    const int tid = threadIdx.x;
    if (blockIdx.x < 6144) {
        __shared__ float tmax[144];
        const int nc = blockIdx.x;
        const int n = nc / 3, c = nc % 3;
        const float* img = frames + (size_t)nc * 9216;
        if (tid < 144) {
            const int ti = tid / 12, tj = tid % 12;
            const float* p = img + ti * 8 * 96 + tj * 8;
            float m = -3.402823466e38f;
#pragma unroll
            for (int r = 0; r < 8; r++) {
                float4 v0 = *(const float4*)(p + r * 96);
                float4 v1 = *(const float4*)(p + r * 96 + 4);
                m = fmaxf(m, fmaxf(fmaxf(v0.x, v0.y), fmaxf(v0.z, v0.w)));
                m = fmaxf(m, fmaxf(fmaxf(v1.x, v1.y), fmaxf(v1.z, v1.w)));
            }
            tmax[tid] = m;
        }
        __syncthreads();
        float* orow = pooled + (size_t)n * 90;
        if (tid < 16) {
            int i = tid / 4, j = tid % 4;
            float m = -3.402823466e38f;
            for (int a = 0; a < 3; a++) for (int b = 0; b < 3; b++)
                m = fmaxf(m, tmax[(i * 3 + a) * 12 + (j * 3 + b)]);
            orow[c * 16 + i * 4 + j] = m;
        } else if (tid < 25) {
            int q = tid - 16, i = q / 3, j = q % 3;
            float m = -3.402823466e38f;
            for (int a = 0; a < 4; a++) for (int b = 0; b < 4; b++)
                m = fmaxf(m, tmax[(i * 4 + a) * 12 + (j * 4 + b)]);
            orow[48 + c * 9 + i * 3 + j] = m;
        } else if (tid < 29) {
            int q = tid - 25, i = q / 2, j = q % 2;
            float m = -3.402823466e38f;
            for (int a = 0; a < 6; a++) for (int b = 0; b < 6; b++)
                m = fmaxf(m, tmax[(i * 6 + a) * 12 + (j * 6 + b)]);
            orow[75 + c * 4 + i * 2 + j] = m;
        } else if (tid == 29) {
            float m = -3.402823466e38f;
            for (int a = 0; a < 144; a++) m = fmaxf(m, tmax[a]);
            orow[87 + c] = m;
        }
        return;
    }
    const int blk = blockIdx.x - 6144;
    if (blk < 512) {
        int o = blk * 256 + tid;
        int i = o >> 5, j = o & 31;
        float s = 0.f;
        for (int p = 0; p < 90; p++) s += spp_w[i * 90 + p] * fw[p * 32 + j];
        g_G[o] = s;
    } else if (blk < 528) {
        int i = (blk - 512) * 256 + tid;
        float s = spp_b[i];
        for (int p = 0; p < 90; p++) s += spp_w[i * 90 + p] * fb[p];
        g_cvec[i] = s;
    } else if (blk == 528) {
        g_b1c[tid] = b1i[tid] + b1h[tid];
        if (tid < 128) g_b2c[tid] = b2i[tid] + b2h[tid];
    } else if (blk == 529) {
        for (int idx = tid; idx < 12288; idx += 256) {
            int g = idx / 96, k = idx - g * 96;
            g_Wcat2[idx] = (k < 64) ? w2i[g * 64 + k] : w2h[g * 32 + (k - 64)];
        }
    } else if (blk == 530) {
        for (int idx = tid; idx < 8192; idx += 256) {
            int k = idx >> 8, r = idx & 255;
            g_w1hP[idx] = pack2f(w1h[r * 64 + 2 * k], w1h[r * 64 + 2 * k + 1]);
        }
    } else if (blk == 531) {
        for (int idx = tid; idx < 6144; idx += 256) {
            int k = idx >> 7, r = idx & 127;
            ull v;
            if (k < 32) v = pack2f(w2i[r * 64 + 2 * k], w2i[r * 64 + 2 * k + 1]);
            else { int k2 = k - 32; v = pack2f(w2h[r * 32 + 2 * k2], w2h[r * 32 + 2 * k2 + 1]); }
            g_w2P[idx] = v;
        }
    }
}

// ---------------- fused two-layer MLP with split-K over the 4096 hidden dim ----------------
template<int KA>
__global__ void __launch_bounds__(256) fused_mlp(
        const float* __restrict__ A, int lda,
        const float* __restrict__ W1, const float* __restrict__ b1,
        const float* __restrict__ fc7, float* __restrict__ part) {
    constexpr int KAP = (KA == 90) ? 90 : 34;
    constexpr int WS  = (KA == 90) ? 90 : 34;
    constexpr int NW  = (32 * KA + 255) / 256;
    extern __shared__ float sm[];
    float* A2 = sm;                       // [128][KAP]
    float* W2 = A2 + 128 * KAP;           // [32][WS]
    float* F2 = W2 + 32 * WS;             // [64][36] swizzled
    float* Es = F2 + 64 * 36;             // [128][40] swizzled
    const int tid = threadIdx.x;
    const int s = blockIdx.x, m0 = blockIdx.y * 128;
    for (int idx = tid; idx < 128 * KA; idx += 256) {
        int r = idx / KA, p = idx - r * KA;
        A2[r * KAP + p] = A[(size_t)(m0 + r) * lda + p];
    }
    ull acc2[8][4];
#pragma unroll
    for (int i = 0; i < 8; i++)
#pragma unroll
        for (int j = 0; j < 4; j++) acc2[i][j] = 0ull;
    const int kbase = s * 256;
    const int txE = tid & 7, tyE = tid >> 3;
    const int txM = tid & 15, tyM = tid >> 4;
    const int eswM = 4 * (tyM & 7);
    const int fswM = 4 * (txM & 7);

    float pw[NW], pf[8];
#pragma unroll
    for (int i = 0; i < NW; i++) {
        int idx = tid + i * 256;
        if (idx < 32 * KA) pw[i] = W1[(size_t)(kbase + idx / KA) * KA + idx % KA];
    }
#pragma unroll
    for (int i = 0; i < 8; i++) {
        int idx = tid + i * 256;
        pf[i] = fc7[(size_t)(idx >> 5) * 4096 + kbase + (idx & 31)];
    }

    for (int kc = 0; kc < 256; kc += 32) {
        const int cg0 = kbase + kc;
        __syncthreads();
#pragma unroll
        for (int i = 0; i < NW; i++) {
            int idx = tid + i * 256;
            if (idx < 32 * KA) W2[(idx / KA) * WS + idx % KA] = pw[i];
        }
#pragma unroll
        for (int i = 0; i < 8; i++) {
            int idx = tid + i * 256;
            int n = idx >> 5, kk = idx & 31;
            F2[n * 36 + (kk ^ (4 * ((n >> 2) & 7)))] = pf[i];
        }
        __syncthreads();
        if (kc + 32 < 256) {
            const int ng0 = cg0 + 32;
#pragma unroll
            for (int i = 0; i < NW; i++) {
                int idx = tid + i * 256;
                if (idx < 32 * KA) pw[i] = W1[(size_t)(ng0 + idx / KA) * KA + idx % KA];
            }
#pragma unroll
            for (int i = 0; i < 8; i++) {
                int idx = tid + i * 256;
                pf[i] = fc7[(size_t)(idx >> 5) * 4096 + ng0 + (idx & 31)];
            }
        }
        ull e2[4][4];
#pragma unroll
        for (int i = 0; i < 4; i++)
#pragma unroll
            for (int j = 0; j < 4; j++) e2[i][j] = 0ull;
#pragma unroll 15
        for (int p = 0; p < KA; p += 2) {
            ull a0 = *(const ull*)&A2[(tyE * 4 + 0) * KAP + p];
            ull a1 = *(const ull*)&A2[(tyE * 4 + 1) * KAP + p];
            ull a2 = *(const ull*)&A2[(tyE * 4 + 2) * KAP + p];
            ull a3 = *(const ull*)&A2[(tyE * 4 + 3) * KAP + p];
            ull w0 = *(const ull*)&W2[(txE * 4 + 0) * WS + p];
            ull w1 = *(const ull*)&W2[(txE * 4 + 1) * WS + p];
            ull w2 = *(const ull*)&W2[(txE * 4 + 2) * WS + p];
            ull w3 = *(const ull*)&W2[(txE * 4 + 3) * WS + p];
            ffma2(e2[0][0], a0, w0); ffma2(e2[0][1], a0, w1);
            ffma2(e2[0][2], a0, w2); ffma2(e2[0][3], a0, w3);
            ffma2(e2[1][0], a1, w0); ffma2(e2[1][1], a1, w1);
            ffma2(e2[1][2], a1, w2); ffma2(e2[1][3], a1, w3);
            ffma2(e2[2][0], a2, w0); ffma2(e2[2][1], a2, w1);
            ffma2(e2[2][2], a2, w2); ffma2(e2[2][3], a2, w3);
            ffma2(e2[3][0], a3, w0); ffma2(e2[3][1], a3, w1);
            ffma2(e2[3][2], a3, w2); ffma2(e2[3][3], a3, w3);
        }
#pragma unroll
        for (int i = 0; i < 4; i++) {
            int r = tyE * 4 + i;
            int swz = 4 * ((r >> 3) & 7);
#pragma unroll
            for (int j = 0; j < 4; j++) {
                int c = txE * 4 + j;
                float2 f = unpack2f(e2[i][j]);
                float v = f.x + f.y + b1[cg0 + c];
                Es[r * 40 + (c ^ swz)] = fmaxf(v, 0.f);
            }
        }
        __syncthreads();
#pragma unroll
        for (int kk = 0; kk < 32; kk += 2) {
            ull e[8], fv[4];
#pragma unroll
            for (int i = 0; i < 8; i++)
                e[i] = *(const ull*)&Es[(tyM * 8 + i) * 40 + (kk ^ eswM)];
#pragma unroll
            for (int j = 0; j < 4; j++)
                fv[j] = *(const ull*)&F2[(txM * 4 + j) * 36 + (kk ^ fswM)];
#pragma unroll
            for (int i = 0; i < 8; i++)
#pragma unroll
                for (int j = 0; j < 4; j++) ffma2(acc2[i][j], e[i], fv[j]);
        }
    }
#pragma unroll
    for (int i = 0; i < 8; i++)
#pragma unroll
        for (int j = 0; j < 4; j++) {
            float2 f = unpack2f(acc2[i][j]);
            part[((size_t)s * NROWS + m0 + tyM * 8 + i) * 64 + txM * 4 + j] = f.x + f.y;
        }
}

// ---------------- reduce partials -> emb, then XP = emb@w1i^T + b1c ----------------
__global__ void __launch_bounds__(256) reduce_xp(const float* __restrict__ fc7_b,
                                                 const float* __restrict__ w1i) {
    extern __shared__ float dsm[];
    float* wS   = dsm;              // [256][66]
    float* embS = dsm + 256 * 66;   // [16][66]
    const int tid = threadIdx.x;
    const int r0 = blockIdx.x * 16;
    {
        int r = tid >> 4, ng = tid & 15;
        float4 acc = *(const float4*)&fc7_b[ng * 4];
#pragma unroll
        for (int ss = 0; ss < SPLITS; ss++) {
            float4 v = *(const float4*)&g_part[((size_t)ss * NROWS + r0 + r) * 64 + ng * 4];
            acc.x += v.x; acc.y += v.y; acc.z += v.z; acc.w += v.w;
        }
        embS[r * 66 + ng * 4 + 0] = fmaxf(acc.x, 0.f);
        embS[r * 66 + ng * 4 + 1] = fmaxf(acc.y, 0.f);
        embS[r * 66 + ng * 4 + 2] = fmaxf(acc.z, 0.f);
        embS[r * 66 + ng * 4 + 3] = fmaxf(acc.w, 0.f);
    }
    for (int idx = tid; idx < 16384; idx += 256)
        wS[(idx >> 6) * 66 + (idx & 63)] = w1i[idx];
    __syncthreads();
    ull w[32];
#pragma unroll
    for (int k = 0; k < 32; k++) w[k] = *(const ull*)&wS[tid * 66 + 2 * k];
    const float bias = g_b1c[tid];
    for (int r = 0; r < 16; r += 2) {
        ull a0 = pack2f(bias, 0.f), a1 = 0ull;
        ull c0 = pack2f(bias, 0.f), c1 = 0ull;
#pragma unroll
        for (int k = 0; k < 16; k++) {
            ffma2(a0, w[2 * k],     *(const ull*)&embS[r * 66 + 4 * k]);
            ffma2(a1, w[2 * k + 1], *(const ull*)&embS[r * 66 + 4 * k + 2]);
            ffma2(c0, w[2 * k],     *(const ull*)&embS[(r + 1) * 66 + 4 * k]);
            ffma2(c1, w[2 * k + 1], *(const ull*)&embS[(r + 1) * 66 + 4 * k + 2]);
        }
        float2 f0 = unpack2f(a0), f1 = unpack2f(a1);
        float2 g0 = unpack2f(c0), g1 = unpack2f(c1);
        g_XP[(size_t)(r0 + r) * 256 + tid]     = (f0.x + f0.y) + (f1.x + f1.y);
        g_XP[(size_t)(r0 + r + 1) * 256 + tid] = (g0.x + g0.y) + (g1.x + g1.y);
    }
}

// ---------------- reduce fe partials; gates1f = [fe|h1]@[w1i|w1h]^T + b1c -> g_XP ----------------
__global__ void __launch_bounds__(256) reduce_gates(const float* __restrict__ fc7_b,
                                                    const float* __restrict__ w1i,
                                                    const float* __restrict__ w1h) {
    extern __shared__ float dsm[];
    float* wS = dsm;                // [256][130]
    float* S  = dsm + 256 * 130;    // [16][132]
    const int tid = threadIdx.x;
    const int r0 = blockIdx.x * 16;
    {
        int r = tid >> 4, ng = tid & 15;
        float4 acc = *(const float4*)&fc7_b[ng * 4];
#pragma unroll
        for (int ss = 0; ss < SPLITS; ss++) {
            float4 v = *(const float4*)&g_part[((size_t)ss * NROWS + r0 + r) * 64 + ng * 4];
            acc.x += v.x; acc.y += v.y; acc.z += v.z; acc.w += v.w;
        }
        S[r * 132 + ng * 4 + 0] = fmaxf(acc.x, 0.f);
        S[r * 132 + ng * 4 + 1] = fmaxf(acc.y, 0.f);
        S[r * 132 + ng * 4 + 2] = fmaxf(acc.z, 0.f);
        S[r * 132 + ng * 4 + 3] = fmaxf(acc.w, 0.f);
        float4 h = *(const float4*)&g_states[(size_t)(r0 + r) * 192 + ng * 4];
        *(float4*)&S[r * 132 + 64 + ng * 4] = h;
    }
    for (int idx = tid; idx < 16384; idx += 256) {
        wS[(idx >> 6) * 130 + (idx & 63)]      = w1i[idx];
        wS[(idx >> 6) * 130 + 64 + (idx & 63)] = w1h[idx];
    }
    __syncthreads();
    ull wc[64];
#pragma unroll
    for (int k = 0; k < 64; k++) wc[k] = *(const ull*)&wS[tid * 130 + 2 * k];
    const float bias = g_b1c[tid];
    for (int r = 0; r < 16; r += 2) {
        ull a0 = pack2f(bias, 0.f), a1 = 0ull;
        ull c0 = pack2f(bias, 0.f), c1 = 0ull;
#pragma unroll
        for (int k = 0; k < 32; k++) {
            ffma2(a0, wc[2 * k],     *(const ull*)&S[r * 132 + 4 * k]);
            ffma2(a1, wc[2 * k + 1], *(const ull*)&S[r * 132 + 4 * k + 2]);
            ffma2(c0, wc[2 * k],     *(const ull*)&S[(r + 1) * 132 + 4 * k]);
            ffma2(c1, wc[2 * k + 1], *(const ull*)&S[(r + 1) * 132 + 4 * k + 2]);
        }
        float2 f0 = unpack2f(a0), f1 = unpack2f(a1);
        float2 g0 = unpack2f(c0), g1 = unpack2f(c1);
        g_XP[(size_t)(r0 + r) * 256 + tid]     = (f0.x + f0.y) + (f1.x + f1.y);
        g_XP[(size_t)(r0 + r + 1) * 256 + tid] = (g0.x + g0.y) + (g1.x + g1.y);
    }
}

// ---------------- warp-specialized LSTM scan, 2 batches per block ----------------
// group (256 threads) per batch; named barrier per group; warps 0-3 lstm1, 4-7 lstm2.
__global__ void __launch_bounds__(512, 1) scan_kernel() {
    __shared__ __align__(16) float h1s[2][2][64];   // [group][buf][j]
    __shared__ __align__(16) float h2s[2][2][32];
    const int tid = threadIdx.x;
    const int grp = tid >> 8;
    const int gtid = tid & 255;
    const int wid = gtid >> 5, lane = tid & 31;
    const int b = blockIdx.x * 2 + grp;
    const int barid = 1 + grp;
    const float* xp = g_XP + (size_t)b * 65536;
    float* st = g_states + (size_t)b * 49152;

    ull wreg[64];
    float bc2 = 0.f, cst = 0.f;
    int p = 0, q = 0, jj = 0, rA = 0, rB = 0;
    if (wid < 4) {
        p = lane & 1;
        jj = (wid << 4) + (lane >> 1);
        rA = p ? (128 + jj) : jj;
        rB = rA + 64;
#pragma unroll
        for (int k = 0; k < 32; k++) {
            wreg[k]      = g_w1hP[k * 256 + rA];
            wreg[32 + k] = g_w1hP[k * 256 + rB];
        }
    } else {
        q = lane & 3;
        jj = ((wid - 4) << 3) + (lane >> 2);
        int r = (q << 5) + jj;
#pragma unroll
        for (int k = 0; k < 48; k++) wreg[k] = g_w2P[k * 128 + r];
        bc2 = g_b2c[r];
    }
    if (gtid < 64) { h1s[grp][0][gtid] = 0.f; h1s[grp][1][gtid] = 0.f; }
    if (gtid >= 64 && gtid < 96) { h2s[grp][0][gtid - 64] = 0.f; h2s[grp][1][gtid - 64] = 0.f; }
    float xA = 0.f, xB = 0.f;
    if (wid < 4) { xA = xp[rA]; xB = xp[rB]; }
    __syncthreads();

    for (int t = 0; t <= 256; t++) {
        const int buf = t & 1;
        if (wid < 4) {
            if (t < 256) {
                float xAn = 0.f, xBn = 0.f;
                if (t + 1 < 256) {
                    xAn = xp[(t + 1) * 256 + rA];
                    xBn = xp[(t + 1) * 256 + rB];
                }
                const float* hb = h1s[grp][buf];
                ull a0 = pack2f(xA, 0.f), a1 = 0ull;
                ull b0 = pack2f(xB, 0.f), b1 = 0ull;
#pragma unroll
                for (int k = 0; k < 16; k++) {
                    ulonglong2 h = *(const ulonglong2*)&hb[4 * k];
                    ffma2(a0, wreg[2 * k],      h.x); ffma2(a1, wreg[2 * k + 1],      h.y);
                    ffma2(b0, wreg[32 + 2 * k], h.x); ffma2(b1, wreg[32 + 2 * k + 1], h.y);
                }
                float2 fa0 = unpack2f(a0), fa1 = unpack2f(a1);
                float2 fb0 = unpack2f(b0), fb1 = unpack2f(b1);
                float gA = (fa0.x + fa0.y) + (fa1.x + fa1.y);
                float gB = (fb0.x + fb0.y) + (fb1.x + fb1.y);
                float actA = p ? tanh_f(gA) : sig_f(gA);   // p0: i, p1: g
                float actB = sig_f(gB);                    // p0: f, p1: o
                float gg = __shfl_xor_sync(0xffffffffu, actA, 1);
                float oo = __shfl_xor_sync(0xffffffffu, actB, 1);
                if (p == 0) {
                    float c = actB * cst + actA * gg;
                    float h = oo * tanh_f(c);
                    cst = c;
                    h1s[grp][buf ^ 1][jj] = h;
                    st[t * 192 + jj] = h;
                    st[t * 192 + 64 + jj] = c;
                }
                xA = xAn; xB = xBn;
            }
        } else if (t >= 1) {
            const int tp = t - 1;
            const float* hb1 = h1s[grp][buf];
            const float* hb2 = h2s[grp][buf];
            ull a0 = pack2f(bc2, 0.f), a1 = 0ull;
#pragma unroll
            for (int k = 0; k < 16; k++) {
                ulonglong2 h = *(const ulonglong2*)&hb1[4 * k];
                ffma2(a0, wreg[2 * k], h.x); ffma2(a1, wreg[2 * k + 1], h.y);
            }
#pragma unroll
            for (int k = 0; k < 8; k++) {
                ulonglong2 h = *(const ulonglong2*)&hb2[4 * k];
                ffma2(a0, wreg[32 + 2 * k], h.x); ffma2(a1, wreg[32 + 2 * k + 1], h.y);
            }
            float2 f0 = unpack2f(a0), f1 = unpack2f(a1);
            float g = (f0.x + f0.y) + (f1.x + f1.y);
            float act = (q == 2) ? tanh_f(g) : sig_f(g);
            const int base = lane & ~3;
            float fi = __shfl_sync(0xffffffffu, act, base + 0);
            float ff = __shfl_sync(0xffffffffu, act, base + 1);
            float fg = __shfl_sync(0xffffffffu, act, base + 2);
            float fo = __shfl_sync(0xffffffffu, act, base + 3);
            if (q == 0) {
                float c = ff * cst + fi * fg;
                float h = fo * tanh_f(c);
                cst = c;
                h2s[grp][buf ^ 1][jj] = h;
                st[tp * 192 + 128 + jj] = h;
                st[tp * 192 + 160 + jj] = c;
            }
        }
        asm volatile("bar.sync %0, 256;" :: "r"(barid) : "memory");
    }
}

// ---------------- fused tail: flstm1 + gates2f + heads + fpool ----------------
__global__ void __launch_bounds__(128) tail_kernel(
        const float* __restrict__ fc8w, const float* __restrict__ fc8b,
        const float* __restrict__ fw, const float* __restrict__ fb,
        float* __restrict__ out, float* __restrict__ fpooled) {
    extern __shared__ float dsm[];
    float* wcS = dsm;               // [128][98]
    float* fwS = dsm + 128 * 98;    // [90][34]
    __shared__ float fh1[64], h2s[32], c2s[32], gs[128];
    const int tid = threadIdx.x;
    for (int idx = tid; idx < 12288; idx += 128)
        wcS[(idx / 96) * 98 + idx % 96] = g_Wcat2[idx];
    for (int idx = tid; idx < 2880; idx += 128)
        fwS[(idx >> 5) * 34 + (idx & 31)] = fw[idx];
    __syncthreads();
    float wcat[96];
#pragma unroll
    for (int k = 0; k < 96; k++) wcat[k] = wcS[tid * 98 + k];
    const float b2 = g_b2c[tid];
    const int po = tid - 32;
    float fwr[32];
    if (po >= 0 && po < 90) {
#pragma unroll
        for (int k = 0; k < 32; k++) fwr[k] = fwS[po * 34 + k];
    }
    const float w8 = (tid < 32) ? fc8w[tid] : 0.f;
    const float b8 = fc8b[0];
    const bool is_tanh2 = (tid >= 64 && tid < 96);

    for (int r = 0; r < 16; r++) {
        const int row = blockIdx.x * 16 + r;
        const float* xpf = g_XP + (size_t)row * 256;
        const float* st = g_states + (size_t)row * 192;
        if (tid < 64) {
            float i = sig_f(xpf[tid]);
            float f = sig_f(xpf[64 + tid]);
            float gg = tanh_f(xpf[128 + tid]);
            float o = sig_f(xpf[192 + tid]);
            float cn = f * st[64 + tid] + i * gg;
            fh1[tid] = o * tanh_f(cn);
        } else if (tid < 96) {
            h2s[tid - 64] = st[128 + (tid - 64)];
        } else {
            c2s[tid - 96] = st[160 + (tid - 96)];
        }
        __syncthreads();
        float a = b2;
#pragma unroll
        for (int k = 0; k < 64; k++) a += wcat[k] * fh1[k];
#pragma unroll
        for (int k = 0; k < 32; k++) a += wcat[64 + k] * h2s[k];
        gs[tid] = is_tanh2 ? tanh_f(a) : sig_f(a);
        __syncthreads();
        if (tid < 32) {
            float cn = gs[32 + tid] * c2s[tid] + gs[tid] * gs[64 + tid];
            float fh2 = gs[96 + tid] * tanh_f(cn);
            float v1 = h2s[tid] * w8;
            float v2 = fh2 * w8;
#pragma unroll
            for (int off = 16; off > 0; off >>= 1) {
                v1 += __shfl_down_sync(0xffffffffu, v1, off);
                v2 += __shfl_down_sync(0xffffffffu, v2, off);
            }
            if (tid == 0) {
                out[row] = sig_f(v1 + b8);
                out[NROWS + row] = sig_f(v2 + b8);
            }
        } else if (po < 90) {
            float s2 = fb[po];
#pragma unroll
            for (int k = 0; k < 32; k++) s2 += fwr[k] * h2s[k];
            fpooled[(size_t)row * 90 + po] = s2;
        }
        __syncthreads();
    }
}

// ---------------- host ----------------
extern "C" void kernel_launch(void* const* d_in, const int* in_sizes, int n_in,
                              void* d_out, int out_size) {
    const float* frames = (const float*)d_in[0];
    const float* spp_w  = (const float*)d_in[1];
    const float* spp_b  = (const float*)d_in[2];
    const float* fc7_w  = (const float*)d_in[3];
    const float* fc7_b  = (const float*)d_in[4];
    const float* w1i    = (const float*)d_in[5];
    const float* w1h    = (const float*)d_in[6];
    const float* b1i    = (const float*)d_in[7];
    const float* b1h    = (const float*)d_in[8];
    const float* w2i    = (const float*)d_in[9];
    const float* w2h    = (const float*)d_in[10];
    const float* b2i    = (const float*)d_in[11];
    const float* b2h    = (const float*)d_in[12];
    const float* fw     = (const float*)d_in[13];
    const float* fb     = (const float*)d_in[14];
    const float* fc8w   = (const float*)d_in[15];
    const float* fc8b   = (const float*)d_in[16];
    float* out = (float*)d_out;

    float *PART, *ST, *G, *CV;
    cudaGetSymbolAddress((void**)&PART, g_part);
    cudaGetSymbolAddress((void**)&ST, g_states);
    cudaGetSymbolAddress((void**)&G, g_G);
    cudaGetSymbolAddress((void**)&CV, g_cvec);

    const int SM1 = (128 * 90 + 32 * 90 + 64 * 36 + 128 * 40) * 4;
    const int SM2 = (128 * 34 + 32 * 34 + 64 * 36 + 128 * 40) * 4;
    const int SMRX = (256 * 66 + 16 * 66) * 4;
    const int SMRG = (256 * 130 + 16 * 132) * 4;
    const int SMT  = (128 * 98 + 90 * 34) * 4;
    cudaFuncSetAttribute(fused_mlp<90>, cudaFuncAttributeMaxDynamicSharedMemorySize, SM1);
    cudaFuncSetAttribute(fused_mlp<32>, cudaFuncAttributeMaxDynamicSharedMemorySize, SM2);
    cudaFuncSetAttribute(reduce_xp, cudaFuncAttributeMaxDynamicSharedMemorySize, SMRX);
    cudaFuncSetAttribute(reduce_gates, cudaFuncAttributeMaxDynamicSharedMemorySize, SMRG);
    cudaFuncSetAttribute(tail_kernel, cudaFuncAttributeMaxDynamicSharedMemorySize, SMT);

    float* pooled  = out + 2 * NROWS;
    float* fpooled = out + 2 * NROWS + NROWS * 90;

    spp_prep<<<6676, 256>>>(frames, pooled, spp_w, spp_b, fw, fb,
                            b1i, b1h, w1h, w2i, w2h, b2i, b2h);
    fused_mlp<90><<<dim3(SPLITS, 16), 256, SM1>>>(pooled, 90, spp_w, spp_b, fc7_w, PART);
    reduce_xp<<<128, 256, SMRX>>>(fc7_b, w1i);
    scan_kernel<<<4, 512>>>();
    fused_mlp<32><<<dim3(SPLITS, 16), 256, SM2>>>(ST + 128, 192, G, CV, fc7_w, PART);
    reduce_gates<<<128, 256, SMRG>>>(fc7_b, w1i, w1h);
    tail_kernel<<<128, 128, SMT>>>(fc8w, fc8b, fw, fb, out, fpooled);
}

// round 10
// speedup vs baseline: 1.0953x; 1.0953x over previous
#include <cuda_runtime.h>
#include <cuda_bf16.h>
#include <math.h>

#define NROWS 2048
#define EMBED 4096
#define SPLITS 16

typedef unsigned long long ull;

__device__ __forceinline__ void ffma2(ull& d, ull a, ull b) {
    asm("fma.rn.f32x2 %0, %1, %2, %3;" : "=l"(d) : "l"(a), "l"(b), "l"(d));
}
__device__ __forceinline__ ull pack2f(float x, float y) {
    ull r; asm("mov.b64 %0, {%1, %2};" : "=l"(r) : "f"(x), "f"(y)); return r;
}
__device__ __forceinline__ float2 unpack2f(ull v) {
    float2 f; asm("mov.b64 {%0, %1}, %2;" : "=f"(f.x), "=f"(f.y) : "l"(v)); return f;
}

// ---------------- scratch ----------------
__device__ float g_part[SPLITS * NROWS * 64];
__device__ float g_XP[NROWS * 256];
__device__ float g_states[NROWS * 192];   // per row: h1[64] c1[64] h2[32] c2[32]
__device__ float g_G[EMBED * 32];
__device__ float g_cvec[EMBED];
__device__ float g_Wcat2[128 * 96];
__device__ float g_b1c[256];
__device__ float g_b2c[128];

__device__ __forceinline__ float sig_f(float x) {
    return __fdividef(1.0f, 1.0f + __expf(-x));
}
__device__ __forceinline__ float tanh_f(float x) {
    return __fdividef(2.0f, 1.0f + __expf(-2.0f * x)) - 1.0f;
}

// ---------------- merged SPP + prep ----------------
__global__ void spp_prep(const float* __restrict__ frames, float* __restrict__ pooled,
                         const float* __restrict__ spp_w, const float* __restrict__ spp_b,
                         const float* __restrict__ fw, const float* __restrict__ fb,
                         const float* __restrict__ b1i, const float* __restrict__ b1h,
                         const float* __restrict__ w2i, const float* __restrict__ w2h,
                         const float* __restrict__ b2i, const float* __restrict__ b2h) {
    const int tid = threadIdx.x;
    if (blockIdx.x < 6144) {
        __shared__ float tmax[144];
        const int nc = blockIdx.x;
        const int n = nc / 3, c = nc % 3;
        const float* img = frames + (size_t)nc * 9216;
        if (tid < 144) {
            const int ti = tid / 12, tj = tid % 12;
            const float* p = img + ti * 8 * 96 + tj * 8;
            float m = -3.402823466e38f;
#pragma unroll
            for (int r = 0; r < 8; r++) {
                float4 v0 = *(const float4*)(p + r * 96);
                float4 v1 = *(const float4*)(p + r * 96 + 4);
                m = fmaxf(m, fmaxf(fmaxf(v0.x, v0.y), fmaxf(v0.z, v0.w)));
                m = fmaxf(m, fmaxf(fmaxf(v1.x, v1.y), fmaxf(v1.z, v1.w)));
            }
            tmax[tid] = m;
        }
        __syncthreads();
        float* orow = pooled + (size_t)n * 90;
        if (tid < 16) {
            int i = tid / 4, j = tid % 4;
            float m = -3.402823466e38f;
            for (int a = 0; a < 3; a++) for (int b = 0; b < 3; b++)
                m = fmaxf(m, tmax[(i * 3 + a) * 12 + (j * 3 + b)]);
            orow[c * 16 + i * 4 + j] = m;
        } else if (tid < 25) {
            int q = tid - 16, i = q / 3, j = q % 3;
            float m = -3.402823466e38f;
            for (int a = 0; a < 4; a++) for (int b = 0; b < 4; b++)
                m = fmaxf(m, tmax[(i * 4 + a) * 12 + (j * 4 + b)]);
            orow[48 + c * 9 + i * 3 + j] = m;
        } else if (tid < 29) {
            int q = tid - 25, i = q / 2, j = q % 2;
            float m = -3.402823466e38f;
            for (int a = 0; a < 6; a++) for (int b = 0; b < 6; b++)
                m = fmaxf(m, tmax[(i * 6 + a) * 12 + (j * 6 + b)]);
            orow[75 + c * 4 + i * 2 + j] = m;
        } else if (tid == 29) {
            float m = -3.402823466e38f;
            for (int a = 0; a < 144; a++) m = fmaxf(m, tmax[a]);
            orow[87 + c] = m;
        }
        return;
    }
    const int blk = blockIdx.x - 6144;
    if (blk < 512) {
        int o = blk * 256 + tid;
        int i = o >> 5, j = o & 31;
        float s = 0.f;
        for (int p = 0; p < 90; p++) s += spp_w[i * 90 + p] * fw[p * 32 + j];
        g_G[o] = s;
    } else if (blk < 528) {
        int i = (blk - 512) * 256 + tid;
        float s = spp_b[i];
        for (int p = 0; p < 90; p++) s += spp_w[i * 90 + p] * fb[p];
        g_cvec[i] = s;
    } else if (blk == 528) {
        g_b1c[tid] = b1i[tid] + b1h[tid];
        if (tid < 128) g_b2c[tid] = b2i[tid] + b2h[tid];
    } else if (blk == 529) {
        for (int idx = tid; idx < 12288; idx += 256) {
            int g = idx / 96, k = idx - g * 96;
            g_Wcat2[idx] = (k < 64) ? w2i[g * 64 + k] : w2h[g * 32 + (k - 64)];
        }
    }
}

// ---------------- fused two-layer MLP, 64-row tiles for 2+ blocks/SM ----------------
template<int KA>
__global__ void __launch_bounds__(256) fused_mlp(
        const float* __restrict__ A, int lda,
        const float* __restrict__ W1, const float* __restrict__ b1,
        const float* __restrict__ fc7, float* __restrict__ part) {
    constexpr int KAP = (KA == 90) ? 90 : 34;
    constexpr int WS  = KAP;
    constexpr int NW  = (32 * KA + 255) / 256;
    extern __shared__ float sm[];
    float* A2 = sm;                       // [64][KAP]
    float* W2 = A2 + 64 * KAP;            // [32][WS]
    float* F2 = W2 + 32 * WS;             // [64][36] swizzled
    float* Es = F2 + 64 * 36;             // [64][40] swizzled
    const int tid = threadIdx.x;
    const int s = blockIdx.x, m0 = blockIdx.y * 64;
    for (int idx = tid; idx < 64 * KA; idx += 256) {
        int r = idx / KA, p = idx - r * KA;
        A2[r * KAP + p] = A[(size_t)(m0 + r) * lda + p];
    }
    ull acc2[4][4];
#pragma unroll
    for (int i = 0; i < 4; i++)
#pragma unroll
        for (int j = 0; j < 4; j++) acc2[i][j] = 0ull;
    const int kbase = s * 256;
    const int txE = tid & 7, tyE = tid >> 3;    // 8 col-groups x 32 row-pairs
    const int txM = tid & 15, tyM = tid >> 4;   // 16 col-groups x 16 row-quads
    const int eswM = 4 * ((tyM >> 1) & 7);
    const int fswM = 4 * (txM & 7);

    float pw[NW], pf[8];
#pragma unroll
    for (int i = 0; i < NW; i++) {
        int idx = tid + i * 256;
        if (idx < 32 * KA) pw[i] = W1[(size_t)(kbase + idx / KA) * KA + idx % KA];
    }
#pragma unroll
    for (int i = 0; i < 8; i++) {
        int idx = tid + i * 256;
        pf[i] = fc7[(size_t)(idx >> 5) * 4096 + kbase + (idx & 31)];
    }

    for (int kc = 0; kc < 256; kc += 32) {
        const int cg0 = kbase + kc;
        __syncthreads();
#pragma unroll
        for (int i = 0; i < NW; i++) {
            int idx = tid + i * 256;
            if (idx < 32 * KA) W2[(idx / KA) * WS + idx % KA] = pw[i];
        }
#pragma unroll
        for (int i = 0; i < 8; i++) {
            int idx = tid + i * 256;
            int n = idx >> 5, kk = idx & 31;
            F2[n * 36 + (kk ^ (4 * ((n >> 2) & 7)))] = pf[i];
        }
        __syncthreads();
        if (kc + 32 < 256) {
            const int ng0 = cg0 + 32;
#pragma unroll
            for (int i = 0; i < NW; i++) {
                int idx = tid + i * 256;
                if (idx < 32 * KA) pw[i] = W1[(size_t)(ng0 + idx / KA) * KA + idx % KA];
            }
#pragma unroll
            for (int i = 0; i < 8; i++) {
                int idx = tid + i * 256;
                pf[i] = fc7[(size_t)(idx >> 5) * 4096 + ng0 + (idx & 31)];
            }
        }
        // ---- E chunk: rows tyE*2..+1, cols txE*4..+3 ----
        ull e2[2][4];
#pragma unroll
        for (int i = 0; i < 2; i++)
#pragma unroll
            for (int j = 0; j < 4; j++) e2[i][j] = 0ull;
#pragma unroll 15
        for (int p = 0; p < KA; p += 2) {
            ull a0 = *(const ull*)&A2[(tyE * 2 + 0) * KAP + p];
            ull a1 = *(const ull*)&A2[(tyE * 2 + 1) * KAP + p];
            ull w0 = *(const ull*)&W2[(txE * 4 + 0) * WS + p];
            ull w1 = *(const ull*)&W2[(txE * 4 + 1) * WS + p];
            ull w2 = *(const ull*)&W2[(txE * 4 + 2) * WS + p];
            ull w3 = *(const ull*)&W2[(txE * 4 + 3) * WS + p];
            ffma2(e2[0][0], a0, w0); ffma2(e2[0][1], a0, w1);
            ffma2(e2[0][2], a0, w2); ffma2(e2[0][3], a0, w3);
            ffma2(e2[1][0], a1, w0); ffma2(e2[1][1], a1, w1);
            ffma2(e2[1][2], a1, w2); ffma2(e2[1][3], a1, w3);
        }
#pragma unroll
        for (int i = 0; i < 2; i++) {
            int r = tyE * 2 + i;
            int swz = 4 * ((r >> 3) & 7);
#pragma unroll
            for (int j = 0; j < 4; j++) {
                int c = txE * 4 + j;
                float2 f = unpack2f(e2[i][j]);
                float v = f.x + f.y + b1[cg0 + c];
                Es[r * 40 + (c ^ swz)] = fmaxf(v, 0.f);
            }
        }
        __syncthreads();
        // ---- micro: acc += Es(64x32) @ F2(64x32)^T ----
#pragma unroll
        for (int kk = 0; kk < 32; kk += 2) {
            ull e[4], fv[4];
#pragma unroll
            for (int i = 0; i < 4; i++)
                e[i] = *(const ull*)&Es[(tyM * 4 + i) * 40 + (kk ^ eswM)];
#pragma unroll
            for (int j = 0; j < 4; j++)
                fv[j] = *(const ull*)&F2[(txM * 4 + j) * 36 + (kk ^ fswM)];
#pragma unroll
            for (int i = 0; i < 4; i++)
#pragma unroll
                for (int j = 0; j < 4; j++) ffma2(acc2[i][j], e[i], fv[j]);
        }
    }
#pragma unroll
    for (int i = 0; i < 4; i++)
#pragma unroll
        for (int j = 0; j < 4; j++) {
            float2 f = unpack2f(acc2[i][j]);
            part[((size_t)s * NROWS + m0 + tyM * 4 + i) * 64 + txM * 4 + j] = f.x + f.y;
        }
}

// ---------------- reduce partials -> emb, then XP = emb@w1i^T + b1c ----------------
__global__ void __launch_bounds__(256) reduce_xp(const float* __restrict__ fc7_b,
                                                 const float* __restrict__ w1i) {
    extern __shared__ float dsm[];
    float* wS   = dsm;              // [256][66]
    float* embS = dsm + 256 * 66;   // [16][66]
    const int tid = threadIdx.x;
    const int r0 = blockIdx.x * 16;
    {
        int r = tid >> 4, ng = tid & 15;
        float4 acc = *(const float4*)&fc7_b[ng * 4];
#pragma unroll
        for (int ss = 0; ss < SPLITS; ss++) {
            float4 v = *(const float4*)&g_part[((size_t)ss * NROWS + r0 + r) * 64 + ng * 4];
            acc.x += v.x; acc.y += v.y; acc.z += v.z; acc.w += v.w;
        }
        embS[r * 66 + ng * 4 + 0] = fmaxf(acc.x, 0.f);
        embS[r * 66 + ng * 4 + 1] = fmaxf(acc.y, 0.f);
        embS[r * 66 + ng * 4 + 2] = fmaxf(acc.z, 0.f);
        embS[r * 66 + ng * 4 + 3] = fmaxf(acc.w, 0.f);
    }
    for (int idx = tid; idx < 16384; idx += 256)
        wS[(idx >> 6) * 66 + (idx & 63)] = w1i[idx];
    __syncthreads();
    ull w[32];
#pragma unroll
    for (int k = 0; k < 32; k++) w[k] = *(const ull*)&wS[tid * 66 + 2 * k];
    const float bias = g_b1c[tid];
    for (int r = 0; r < 16; r += 2) {
        ull a0 = pack2f(bias, 0.f), a1 = 0ull;
        ull c0 = pack2f(bias, 0.f), c1 = 0ull;
#pragma unroll
        for (int k = 0; k < 16; k++) {
            ffma2(a0, w[2 * k],     *(const ull*)&embS[r * 66 + 4 * k]);
            ffma2(a1, w[2 * k + 1], *(const ull*)&embS[r * 66 + 4 * k + 2]);
            ffma2(c0, w[2 * k],     *(const ull*)&embS[(r + 1) * 66 + 4 * k]);
            ffma2(c1, w[2 * k + 1], *(const ull*)&embS[(r + 1) * 66 + 4 * k + 2]);
        }
        float2 f0 = unpack2f(a0), f1 = unpack2f(a1);
        float2 g0 = unpack2f(c0), g1 = unpack2f(c1);
        g_XP[(size_t)(r0 + r) * 256 + tid]     = (f0.x + f0.y) + (f1.x + f1.y);
        g_XP[(size_t)(r0 + r + 1) * 256 + tid] = (g0.x + g0.y) + (g1.x + g1.y);
    }
}

// ---------------- reduce fe partials; gates1f = [fe|h1]@[w1i|w1h]^T + b1c -> g_XP ----------------
__global__ void __launch_bounds__(256) reduce_gates(const float* __restrict__ fc7_b,
                                                    const float* __restrict__ w1i,
                                                    const float* __restrict__ w1h) {
    extern __shared__ float dsm[];
    float* wS = dsm;                // [256][130]
    float* S  = dsm + 256 * 130;    // [16][132]
    const int tid = threadIdx.x;
    const int r0 = blockIdx.x * 16;
    {
        int r = tid >> 4, ng = tid & 15;
        float4 acc = *(const float4*)&fc7_b[ng * 4];
#pragma unroll
        for (int ss = 0; ss < SPLITS; ss++) {
            float4 v = *(const float4*)&g_part[((size_t)ss * NROWS + r0 + r) * 64 + ng * 4];
            acc.x += v.x; acc.y += v.y; acc.z += v.z; acc.w += v.w;
        }
        S[r * 132 + ng * 4 + 0] = fmaxf(acc.x, 0.f);
        S[r * 132 + ng * 4 + 1] = fmaxf(acc.y, 0.f);
        S[r * 132 + ng * 4 + 2] = fmaxf(acc.z, 0.f);
        S[r * 132 + ng * 4 + 3] = fmaxf(acc.w, 0.f);
        float4 h = *(const float4*)&g_states[(size_t)(r0 + r) * 192 + ng * 4];
        *(float4*)&S[r * 132 + 64 + ng * 4] = h;
    }
    for (int idx = tid; idx < 16384; idx += 256) {
        wS[(idx >> 6) * 130 + (idx & 63)]      = w1i[idx];
        wS[(idx >> 6) * 130 + 64 + (idx & 63)] = w1h[idx];
    }
    __syncthreads();
    ull wc[64];
#pragma unroll
    for (int k = 0; k < 64; k++) wc[k] = *(const ull*)&wS[tid * 130 + 2 * k];
    const float bias = g_b1c[tid];
    for (int r = 0; r < 16; r += 2) {
        ull a0 = pack2f(bias, 0.f), a1 = 0ull;
        ull c0 = pack2f(bias, 0.f), c1 = 0ull;
#pragma unroll
        for (int k = 0; k < 32; k++) {
            ffma2(a0, wc[2 * k],     *(const ull*)&S[r * 132 + 4 * k]);
            ffma2(a1, wc[2 * k + 1], *(const ull*)&S[r * 132 + 4 * k + 2]);
            ffma2(c0, wc[2 * k],     *(const ull*)&S[(r + 1) * 132 + 4 * k]);
            ffma2(c1, wc[2 * k + 1], *(const ull*)&S[(r + 1) * 132 + 4 * k + 2]);
        }
        float2 f0 = unpack2f(a0), f1 = unpack2f(a1);
        float2 g0 = unpack2f(c0), g1 = unpack2f(c1);
        g_XP[(size_t)(r0 + r) * 256 + tid]     = (f0.x + f0.y) + (f1.x + f1.y);
        g_XP[(size_t)(r0 + r + 1) * 256 + tid] = (g0.x + g0.y) + (g1.x + g1.y);
    }
}

// ---------------- pipelined LSTM scan (PROVEN 179us VARIANT): lstm1(t) + lstm2(t-1) ----------------
__global__ void __launch_bounds__(384, 1) scan_kernel(
        const float* __restrict__ w1h, const float* __restrict__ w2i,
        const float* __restrict__ w2h, const float* __restrict__ b2i,
        const float* __restrict__ b2h) {
    __shared__ __align__(16) float h1s[64];
    __shared__ __align__(16) float h2s[32];
    __shared__ float act1[256], act2[128];
    const int tid = threadIdx.x;
    const int b = blockIdx.x;
    const float* xp = g_XP + (size_t)b * 65536;
    float* st = g_states + (size_t)b * 49152;

    ull wreg[48];
    float bc2 = 0.f, c1r = 0.f, c2r = 0.f;
    if (tid < 256) {
#pragma unroll
        for (int k = 0; k < 32; k++)
            wreg[k] = pack2f(w1h[tid * 64 + 2 * k], w1h[tid * 64 + 2 * k + 1]);
    } else {
        int g = tid - 256;
#pragma unroll
        for (int k = 0; k < 32; k++)
            wreg[k] = pack2f(w2i[g * 64 + 2 * k], w2i[g * 64 + 2 * k + 1]);
#pragma unroll
        for (int k = 0; k < 16; k++)
            wreg[32 + k] = pack2f(w2h[g * 32 + 2 * k], w2h[g * 32 + 2 * k + 1]);
        bc2 = b2i[g] + b2h[g];
    }
    if (tid < 64) h1s[tid] = 0.f;
    if (tid < 32) h2s[tid] = 0.f;
    __syncthreads();

    float xcur = 0.f, x1 = 0.f;
    if (tid < 256) { xcur = xp[tid]; x1 = xp[256 + tid]; }
    const bool t1tanh = (tid >= 128 && tid < 192);
    const bool t2tanh = (tid >= 320 && tid < 352);

    for (int t = 0; t <= 256; t++) {
        float x2 = 0.f;
        if (tid < 256 && t + 2 < 256) x2 = xp[(t + 2) * 256 + tid];
        if (tid < 256) {
            if (t < 256) {
                ull a0 = pack2f(xcur, 0.f), a1 = 0ull, a2 = 0ull, a3 = 0ull;
#pragma unroll
                for (int k = 0; k < 8; k++) {
                    ffma2(a0, wreg[4 * k + 0], *(const ull*)&h1s[8 * k + 0]);
                    ffma2(a1, wreg[4 * k + 1], *(const ull*)&h1s[8 * k + 2]);
                    ffma2(a2, wreg[4 * k + 2], *(const ull*)&h1s[8 * k + 4]);
                    ffma2(a3, wreg[4 * k + 3], *(const ull*)&h1s[8 * k + 6]);
                }
                float2 f0 = unpack2f(a0), f1 = unpack2f(a1);
                float2 f2 = unpack2f(a2), f3 = unpack2f(a3);
                float g = ((f0.x + f0.y) + (f1.x + f1.y)) + ((f2.x + f2.y) + (f3.x + f3.y));
                act1[tid] = t1tanh ? tanh_f(g) : sig_f(g);
            }
        } else if (t > 0) {
            ull a0 = pack2f(bc2, 0.f), a1 = 0ull, a2 = 0ull, a3 = 0ull;
#pragma unroll
            for (int k = 0; k < 8; k++) {
                ffma2(a0, wreg[4 * k + 0], *(const ull*)&h1s[8 * k + 0]);
                ffma2(a1, wreg[4 * k + 1], *(const ull*)&h1s[8 * k + 2]);
                ffma2(a2, wreg[4 * k + 2], *(const ull*)&h1s[8 * k + 4]);
                ffma2(a3, wreg[4 * k + 3], *(const ull*)&h1s[8 * k + 6]);
            }
#pragma unroll
            for (int k = 0; k < 4; k++) {
                ffma2(a0, wreg[32 + 4 * k + 0], *(const ull*)&h2s[8 * k + 0]);
                ffma2(a1, wreg[32 + 4 * k + 1], *(const ull*)&h2s[8 * k + 2]);
                ffma2(a2, wreg[32 + 4 * k + 2], *(const ull*)&h2s[8 * k + 4]);
                ffma2(a3, wreg[32 + 4 * k + 3], *(const ull*)&h2s[8 * k + 6]);
            }
            float2 f0 = unpack2f(a0), f1 = unpack2f(a1);
            float2 f2 = unpack2f(a2), f3 = unpack2f(a3);
            float g = ((f0.x + f0.y) + (f1.x + f1.y)) + ((f2.x + f2.y) + (f3.x + f3.y));
            act2[tid - 256] = t2tanh ? tanh_f(g) : sig_f(g);
        }
        __syncthreads();
        if (tid < 64) {
            if (t < 256) {
                float c = act1[64 + tid] * c1r + act1[tid] * act1[128 + tid];
                float h = act1[192 + tid] * tanh_f(c);
                c1r = c; h1s[tid] = h;
                st[t * 192 + tid] = h;
                st[t * 192 + 64 + tid] = c;
            }
        } else if (tid < 96 && t > 0) {
            int j = tid - 64, tp = t - 1;
            float c = act2[32 + j] * c2r + act2[j] * act2[64 + j];
            float h = act2[96 + j] * tanh_f(c);
            c2r = c; h2s[j] = h;
            st[tp * 192 + 128 + j] = h;
            st[tp * 192 + 160 + j] = c;
        }
        __syncthreads();
        xcur = x1; x1 = x2;
    }
}

// ---------------- fused tail: flstm1 + gates2f + heads + fpool ----------------
__global__ void __launch_bounds__(128) tail_kernel(
        const float* __restrict__ fc8w, const float* __restrict__ fc8b,
        const float* __restrict__ fw, const float* __restrict__ fb,
        float* __restrict__ out, float* __restrict__ fpooled) {
    extern __shared__ float dsm[];
    float* wcS = dsm;               // [128][98]
    float* fwS = dsm + 128 * 98;    // [90][34]
    __shared__ float fh1[64], h2s[32], c2s[32], gs[128];
    const int tid = threadIdx.x;
    for (int idx = tid; idx < 12288; idx += 128)
        wcS[(idx / 96) * 98 + idx % 96] = g_Wcat2[idx];
    for (int idx = tid; idx < 2880; idx += 128)
        fwS[(idx >> 5) * 34 + (idx & 31)] = fw[idx];
    __syncthreads();
    float wcat[96];
#pragma unroll
    for (int k = 0; k < 96; k++) wcat[k] = wcS[tid * 98 + k];
    const float b2 = g_b2c[tid];
    const int po = tid - 32;
    float fwr[32];
    if (po >= 0 && po < 90) {
#pragma unroll
        for (int k = 0; k < 32; k++) fwr[k] = fwS[po * 34 + k];
    }
    const float w8 = (tid < 32) ? fc8w[tid] : 0.f;
    const float b8 = fc8b[0];
    const bool is_tanh2 = (tid >= 64 && tid < 96);

    for (int r = 0; r < 16; r++) {
        const int row = blockIdx.x * 16 + r;
        const float* xpf = g_XP + (size_t)row * 256;
        const float* st = g_states + (size_t)row * 192;
        if (tid < 64) {
            float i = sig_f(xpf[tid]);
            float f = sig_f(xpf[64 + tid]);
            float gg = tanh_f(xpf[128 + tid]);
            float o = sig_f(xpf[192 + tid]);
            float cn = f * st[64 + tid] + i * gg;
            fh1[tid] = o * tanh_f(cn);
        } else if (tid < 96) {
            h2s[tid - 64] = st[128 + (tid - 64)];
        } else {
            c2s[tid - 96] = st[160 + (tid - 96)];
        }
        __syncthreads();
        float a = b2;
#pragma unroll
        for (int k = 0; k < 64; k++) a += wcat[k] * fh1[k];
#pragma unroll
        for (int k = 0; k < 32; k++) a += wcat[64 + k] * h2s[k];
        gs[tid] = is_tanh2 ? tanh_f(a) : sig_f(a);
        __syncthreads();
        if (tid < 32) {
            float cn = gs[32 + tid] * c2s[tid] + gs[tid] * gs[64 + tid];
            float fh2 = gs[96 + tid] * tanh_f(cn);
            float v1 = h2s[tid] * w8;
            float v2 = fh2 * w8;
#pragma unroll
            for (int off = 16; off > 0; off >>= 1) {
                v1 += __shfl_down_sync(0xffffffffu, v1, off);
                v2 += __shfl_down_sync(0xffffffffu, v2, off);
            }
            if (tid == 0) {
                out[row] = sig_f(v1 + b8);
                out[NROWS + row] = sig_f(v2 + b8);
            }
        } else if (po < 90) {
            float s2 = fb[po];
#pragma unroll
            for (int k = 0; k < 32; k++) s2 += fwr[k] * h2s[k];
            fpooled[(size_t)row * 90 + po] = s2;
        }
        __syncthreads();
    }
}

// ---------------- host ----------------
extern "C" void kernel_launch(void* const* d_in, const int* in_sizes, int n_in,
                              void* d_out, int out_size) {
    const float* frames = (const float*)d_in[0];
    const float* spp_w  = (const float*)d_in[1];
    const float* spp_b  = (const float*)d_in[2];
    const float* fc7_w  = (const float*)d_in[3];
    const float* fc7_b  = (const float*)d_in[4];
    const float* w1i    = (const float*)d_in[5];
    const float* w1h    = (const float*)d_in[6];
    const float* b1i    = (const float*)d_in[7];
    const float* b1h    = (const float*)d_in[8];
    const float* w2i    = (const float*)d_in[9];
    const float* w2h    = (const float*)d_in[10];
    const float* b2i    = (const float*)d_in[11];
    const float* b2h    = (const float*)d_in[12];
    const float* fw     = (const float*)d_in[13];
    const float* fb     = (const float*)d_in[14];
    const float* fc8w   = (const float*)d_in[15];
    const float* fc8b   = (const float*)d_in[16];
    float* out = (float*)d_out;

    float *PART, *ST, *G, *CV;
    cudaGetSymbolAddress((void**)&PART, g_part);
    cudaGetSymbolAddress((void**)&ST, g_states);
    cudaGetSymbolAddress((void**)&G, g_G);
    cudaGetSymbolAddress((void**)&CV, g_cvec);

    const int SM1 = (64 * 90 + 32 * 90 + 64 * 36 + 64 * 40) * 4;   // 54016
    const int SM2 = (64 * 34 + 32 * 34 + 64 * 36 + 64 * 40) * 4;   // 32512
    const int SMRX = (256 * 66 + 16 * 66) * 4;
    const int SMRG = (256 * 130 + 16 * 132) * 4;
    const int SMT  = (128 * 98 + 90 * 34) * 4;
    cudaFuncSetAttribute(fused_mlp<90>, cudaFuncAttributeMaxDynamicSharedMemorySize, SM1);
    cudaFuncSetAttribute(fused_mlp<32>, cudaFuncAttributeMaxDynamicSharedMemorySize, SM2);
    cudaFuncSetAttribute(reduce_xp, cudaFuncAttributeMaxDynamicSharedMemorySize, SMRX);
    cudaFuncSetAttribute(reduce_gates, cudaFuncAttributeMaxDynamicSharedMemorySize, SMRG);
    cudaFuncSetAttribute(tail_kernel, cudaFuncAttributeMaxDynamicSharedMemorySize, SMT);

    float* pooled  = out + 2 * NROWS;
    float* fpooled = out + 2 * NROWS + NROWS * 90;

    spp_prep<<<6674, 256>>>(frames, pooled, spp_w, spp_b, fw, fb,
                            b1i, b1h, w2i, w2h, b2i, b2h);
    fused_mlp<90><<<dim3(SPLITS, 32), 256, SM1>>>(pooled, 90, spp_w, spp_b, fc7_w, PART);
    reduce_xp<<<128, 256, SMRX>>>(fc7_b, w1i);
    scan_kernel<<<8, 384>>>(w1h, w2i, w2h, b2i, b2h);
    fused_mlp<32><<<dim3(SPLITS, 32), 256, SM2>>>(ST + 128, 192, G, CV, fc7_w, PART);
    reduce_gates<<<128, 256, SMRG>>>(fc7_b, w1i, w1h);
    tail_kernel<<<128, 128, SMT>>>(fc8w, fc8b, fw, fb, out, fpooled);
}

// round 11
// speedup vs baseline: 1.3218x; 1.2067x over previous
#include <cuda_runtime.h>
#include <cuda_bf16.h>
#include <math.h>

#define NROWS 2048
#define EMBED 4096
#define SPLITS 16

typedef unsigned long long ull;

__device__ __forceinline__ void ffma2(ull& d, ull a, ull b) {
    asm("fma.rn.f32x2 %0, %1, %2, %3;" : "=l"(d) : "l"(a), "l"(b), "l"(d));
}
__device__ __forceinline__ ull pack2f(float x, float y) {
    ull r; asm("mov.b64 %0, {%1, %2};" : "=l"(r) : "f"(x), "f"(y)); return r;
}
__device__ __forceinline__ float2 unpack2f(ull v) {
    float2 f; asm("mov.b64 {%0, %1}, %2;" : "=f"(f.x), "=f"(f.y) : "l"(v)); return f;
}

// ---------------- scratch ----------------
__device__ float g_part[SPLITS * NROWS * 64];
__device__ float g_XP[NROWS * 256];
__device__ float g_states[NROWS * 192];   // per row: h1[64] c1[64] h2[32] c2[32]
__device__ float g_G[EMBED * 32];
__device__ float g_cvec[EMBED];
__device__ float g_Wcat2[128 * 96];
__device__ float g_b1c[256];
__device__ float g_b2c[128];
__device__ ull g_w1hP[32 * 256];          // k-major packed w1h rows
__device__ ull g_w2P[48 * 128];           // k-major packed [w2i|w2h] rows

__device__ __forceinline__ float sig_f(float x) {
    return __fdividef(1.0f, 1.0f + __expf(-x));
}
__device__ __forceinline__ float tanh_f(float x) {
    return __fdividef(2.0f, 1.0f + __expf(-2.0f * x)) - 1.0f;
}

// ---------------- merged SPP + prep ----------------
__global__ void spp_prep(const float* __restrict__ frames, float* __restrict__ pooled,
                         const float* __restrict__ spp_w, const float* __restrict__ spp_b,
                         const float* __restrict__ fw, const float* __restrict__ fb,
                         const float* __restrict__ b1i, const float* __restrict__ b1h,
                         const float* __restrict__ w1h,
                         const float* __restrict__ w2i, const float* __restrict__ w2h,
                         const float* __restrict__ b2i, const float* __restrict__ b2h) {
    const int tid = threadIdx.x;
    if (blockIdx.x < 6144) {
        __shared__ float tmax[144];
        const int nc = blockIdx.x;
        const int n = nc / 3, c = nc % 3;
        const float* img = frames + (size_t)nc * 9216;
        if (tid < 144) {
            const int ti = tid / 12, tj = tid % 12;
            const float* p = img + ti * 8 * 96 + tj * 8;
            float m = -3.402823466e38f;
#pragma unroll
            for (int r = 0; r < 8; r++) {
                float4 v0 = *(const float4*)(p + r * 96);
                float4 v1 = *(const float4*)(p + r * 96 + 4);
                m = fmaxf(m, fmaxf(fmaxf(v0.x, v0.y), fmaxf(v0.z, v0.w)));
                m = fmaxf(m, fmaxf(fmaxf(v1.x, v1.y), fmaxf(v1.z, v1.w)));
            }
            tmax[tid] = m;
        }
        __syncthreads();
        float* orow = pooled + (size_t)n * 90;
        if (tid < 16) {
            int i = tid / 4, j = tid % 4;
            float m = -3.402823466e38f;
            for (int a = 0; a < 3; a++) for (int b = 0; b < 3; b++)
                m = fmaxf(m, tmax[(i * 3 + a) * 12 + (j * 3 + b)]);
            orow[c * 16 + i * 4 + j] = m;
        } else if (tid < 25) {
            int q = tid - 16, i = q / 3, j = q % 3;
            float m = -3.402823466e38f;
            for (int a = 0; a < 4; a++) for (int b = 0; b < 4; b++)
                m = fmaxf(m, tmax[(i * 4 + a) * 12 + (j * 4 + b)]);
            orow[48 + c * 9 + i * 3 + j] = m;
        } else if (tid < 29) {
            int q = tid - 25, i = q / 2, j = q % 2;
            float m = -3.402823466e38f;
            for (int a = 0; a < 6; a++) for (int b = 0; b < 6; b++)
                m = fmaxf(m, tmax[(i * 6 + a) * 12 + (j * 6 + b)]);
            orow[75 + c * 4 + i * 2 + j] = m;
        } else if (tid == 29) {
            float m = -3.402823466e38f;
            for (int a = 0; a < 144; a++) m = fmaxf(m, tmax[a]);
            orow[87 + c] = m;
        }
        return;
    }
    const int blk = blockIdx.x - 6144;
    if (blk < 512) {
        int o = blk * 256 + tid;
        int i = o >> 5, j = o & 31;
        float s = 0.f;
        for (int p = 0; p < 90; p++) s += spp_w[i * 90 + p] * fw[p * 32 + j];
        g_G[o] = s;
    } else if (blk < 528) {
        int i = (blk - 512) * 256 + tid;
        float s = spp_b[i];
        for (int p = 0; p < 90; p++) s += spp_w[i * 90 + p] * fb[p];
        g_cvec[i] = s;
    } else if (blk == 528) {
        g_b1c[tid] = b1i[tid] + b1h[tid];
        if (tid < 128) g_b2c[tid] = b2i[tid] + b2h[tid];
    } else if (blk == 529) {
        for (int idx = tid; idx < 12288; idx += 256) {
            int g = idx / 96, k = idx - g * 96;
            g_Wcat2[idx] = (k < 64) ? w2i[g * 64 + k] : w2h[g * 32 + (k - 64)];
        }
    } else if (blk == 530) {
        for (int idx = tid; idx < 8192; idx += 256) {
            int k = idx >> 8, r = idx & 255;
            g_w1hP[idx] = pack2f(w1h[r * 64 + 2 * k], w1h[r * 64 + 2 * k + 1]);
        }
    } else if (blk == 531) {
        for (int idx = tid; idx < 6144; idx += 256) {
            int k = idx >> 7, r = idx & 127;
            ull v;
            if (k < 32) v = pack2f(w2i[r * 64 + 2 * k], w2i[r * 64 + 2 * k + 1]);
            else { int k2 = k - 32; v = pack2f(w2h[r * 32 + 2 * k2], w2h[r * 32 + 2 * k2 + 1]); }
            g_w2P[idx] = v;
        }
    }
}

// ---------------- fused two-layer MLP (proven 128-row tile, R6 config) ----------------
template<int KA>
__global__ void __launch_bounds__(256) fused_mlp(
        const float* __restrict__ A, int lda,
        const float* __restrict__ W1, const float* __restrict__ b1,
        const float* __restrict__ fc7, float* __restrict__ part) {
    constexpr int KAP = (KA == 90) ? 90 : 34;
    constexpr int WS  = KAP;
    constexpr int NW  = (32 * KA + 255) / 256;
    extern __shared__ float sm[];
    float* A2 = sm;                       // [128][KAP]
    float* W2 = A2 + 128 * KAP;           // [32][WS]
    float* F2 = W2 + 32 * WS;             // [64][36] swizzled
    float* Es = F2 + 64 * 36;             // [128][40] swizzled
    const int tid = threadIdx.x;
    const int s = blockIdx.x, m0 = blockIdx.y * 128;
    for (int idx = tid; idx < 128 * KA; idx += 256) {
        int r = idx / KA, p = idx - r * KA;
        A2[r * KAP + p] = A[(size_t)(m0 + r) * lda + p];
    }
    ull acc2[8][4];
#pragma unroll
    for (int i = 0; i < 8; i++)
#pragma unroll
        for (int j = 0; j < 4; j++) acc2[i][j] = 0ull;
    const int kbase = s * 256;
    const int txE = tid & 7, tyE = tid >> 3;
    const int txM = tid & 15, tyM = tid >> 4;
    const int eswM = 4 * (tyM & 7);
    const int fswM = 4 * (txM & 7);

    float pw[NW], pf[8];
#pragma unroll
    for (int i = 0; i < NW; i++) {
        int idx = tid + i * 256;
        if (idx < 32 * KA) pw[i] = W1[(size_t)(kbase + idx / KA) * KA + idx % KA];
    }
#pragma unroll
    for (int i = 0; i < 8; i++) {
        int idx = tid + i * 256;
        pf[i] = fc7[(size_t)(idx >> 5) * 4096 + kbase + (idx & 31)];
    }

    for (int kc = 0; kc < 256; kc += 32) {
        const int cg0 = kbase + kc;
        __syncthreads();
#pragma unroll
        for (int i = 0; i < NW; i++) {
            int idx = tid + i * 256;
            if (idx < 32 * KA) W2[(idx / KA) * WS + idx % KA] = pw[i];
        }
#pragma unroll
        for (int i = 0; i < 8; i++) {
            int idx = tid + i * 256;
            int n = idx >> 5, kk = idx & 31;
            F2[n * 36 + (kk ^ (4 * ((n >> 2) & 7)))] = pf[i];
        }
        __syncthreads();
        if (kc + 32 < 256) {
            const int ng0 = cg0 + 32;
#pragma unroll
            for (int i = 0; i < NW; i++) {
                int idx = tid + i * 256;
                if (idx < 32 * KA) pw[i] = W1[(size_t)(ng0 + idx / KA) * KA + idx % KA];
            }
#pragma unroll
            for (int i = 0; i < 8; i++) {
                int idx = tid + i * 256;
                pf[i] = fc7[(size_t)(idx >> 5) * 4096 + ng0 + (idx & 31)];
            }
        }
        ull e2[4][4];
#pragma unroll
        for (int i = 0; i < 4; i++)
#pragma unroll
            for (int j = 0; j < 4; j++) e2[i][j] = 0ull;
#pragma unroll 15
        for (int p = 0; p < KA; p += 2) {
            ull a0 = *(const ull*)&A2[(tyE * 4 + 0) * KAP + p];
            ull a1 = *(const ull*)&A2[(tyE * 4 + 1) * KAP + p];
            ull a2 = *(const ull*)&A2[(tyE * 4 + 2) * KAP + p];
            ull a3 = *(const ull*)&A2[(tyE * 4 + 3) * KAP + p];
            ull w0 = *(const ull*)&W2[(txE * 4 + 0) * WS + p];
            ull w1 = *(const ull*)&W2[(txE * 4 + 1) * WS + p];
            ull w2 = *(const ull*)&W2[(txE * 4 + 2) * WS + p];
            ull w3 = *(const ull*)&W2[(txE * 4 + 3) * WS + p];
            ffma2(e2[0][0], a0, w0); ffma2(e2[0][1], a0, w1);
            ffma2(e2[0][2], a0, w2); ffma2(e2[0][3], a0, w3);
            ffma2(e2[1][0], a1, w0); ffma2(e2[1][1], a1, w1);
            ffma2(e2[1][2], a1, w2); ffma2(e2[1][3], a1, w3);
            ffma2(e2[2][0], a2, w0); ffma2(e2[2][1], a2, w1);
            ffma2(e2[2][2], a2, w2); ffma2(e2[2][3], a2, w3);
            ffma2(e2[3][0], a3, w0); ffma2(e2[3][1], a3, w1);
            ffma2(e2[3][2], a3, w2); ffma2(e2[3][3], a3, w3);
        }
#pragma unroll
        for (int i = 0; i < 4; i++) {
            int r = tyE * 4 + i;
            int swz = 4 * ((r >> 3) & 7);
#pragma unroll
            for (int j = 0; j < 4; j++) {
                int c = txE * 4 + j;
                float2 f = unpack2f(e2[i][j]);
                float v = f.x + f.y + b1[cg0 + c];
                Es[r * 40 + (c ^ swz)] = fmaxf(v, 0.f);
            }
        }
        __syncthreads();
#pragma unroll
        for (int kk = 0; kk < 32; kk += 2) {
            ull e[8], fv[4];
#pragma unroll
            for (int i = 0; i < 8; i++)
                e[i] = *(const ull*)&Es[(tyM * 8 + i) * 40 + (kk ^ eswM)];
#pragma unroll
            for (int j = 0; j < 4; j++)
                fv[j] = *(const ull*)&F2[(txM * 4 + j) * 36 + (kk ^ fswM)];
#pragma unroll
            for (int i = 0; i < 8; i++)
#pragma unroll
                for (int j = 0; j < 4; j++) ffma2(acc2[i][j], e[i], fv[j]);
        }
    }
#pragma unroll
    for (int i = 0; i < 8; i++)
#pragma unroll
        for (int j = 0; j < 4; j++) {
            float2 f = unpack2f(acc2[i][j]);
            part[((size_t)s * NROWS + m0 + tyM * 8 + i) * 64 + txM * 4 + j] = f.x + f.y;
        }
}

// ---------------- reduce partials -> emb, then XP = emb@w1i^T + b1c ----------------
__global__ void __launch_bounds__(256) reduce_xp(const float* __restrict__ fc7_b,
                                                 const float* __restrict__ w1i) {
    extern __shared__ float dsm[];
    float* wS   = dsm;              // [256][66]
    float* embS = dsm + 256 * 66;   // [16][66]
    const int tid = threadIdx.x;
    const int r0 = blockIdx.x * 16;
    {
        int r = tid >> 4, ng = tid & 15;
        float4 acc = *(const float4*)&fc7_b[ng * 4];
#pragma unroll
        for (int ss = 0; ss < SPLITS; ss++) {
            float4 v = *(const float4*)&g_part[((size_t)ss * NROWS + r0 + r) * 64 + ng * 4];
            acc.x += v.x; acc.y += v.y; acc.z += v.z; acc.w += v.w;
        }
        embS[r * 66 + ng * 4 + 0] = fmaxf(acc.x, 0.f);
        embS[r * 66 + ng * 4 + 1] = fmaxf(acc.y, 0.f);
        embS[r * 66 + ng * 4 + 2] = fmaxf(acc.z, 0.f);
        embS[r * 66 + ng * 4 + 3] = fmaxf(acc.w, 0.f);
    }
    for (int idx = tid; idx < 16384; idx += 256)
        wS[(idx >> 6) * 66 + (idx & 63)] = w1i[idx];
    __syncthreads();
    ull w[32];
#pragma unroll
    for (int k = 0; k < 32; k++) w[k] = *(const ull*)&wS[tid * 66 + 2 * k];
    const float bias = g_b1c[tid];
    for (int r = 0; r < 16; r += 2) {
        ull a0 = pack2f(bias, 0.f), a1 = 0ull;
        ull c0 = pack2f(bias, 0.f), c1 = 0ull;
#pragma unroll
        for (int k = 0; k < 16; k++) {
            ffma2(a0, w[2 * k],     *(const ull*)&embS[r * 66 + 4 * k]);
            ffma2(a1, w[2 * k + 1], *(const ull*)&embS[r * 66 + 4 * k + 2]);
            ffma2(c0, w[2 * k],     *(const ull*)&embS[(r + 1) * 66 + 4 * k]);
            ffma2(c1, w[2 * k + 1], *(const ull*)&embS[(r + 1) * 66 + 4 * k + 2]);
        }
        float2 f0 = unpack2f(a0), f1 = unpack2f(a1);
        float2 g0 = unpack2f(c0), g1 = unpack2f(c1);
        g_XP[(size_t)(r0 + r) * 256 + tid]     = (f0.x + f0.y) + (f1.x + f1.y);
        g_XP[(size_t)(r0 + r + 1) * 256 + tid] = (g0.x + g0.y) + (g1.x + g1.y);
    }
}

// ---------------- reduce fe partials; gates1f = [fe|h1]@[w1i|w1h]^T + b1c -> g_XP ----------------
__global__ void __launch_bounds__(256) reduce_gates(const float* __restrict__ fc7_b,
                                                    const float* __restrict__ w1i,
                                                    const float* __restrict__ w1h) {
    extern __shared__ float dsm[];
    float* wS = dsm;                // [256][130]
    float* S  = dsm + 256 * 130;    // [16][132]
    const int tid = threadIdx.x;
    const int r0 = blockIdx.x * 16;
    {
        int r = tid >> 4, ng = tid & 15;
        float4 acc = *(const float4*)&fc7_b[ng * 4];
#pragma unroll
        for (int ss = 0; ss < SPLITS; ss++) {
            float4 v = *(const float4*)&g_part[((size_t)ss * NROWS + r0 + r) * 64 + ng * 4];
            acc.x += v.x; acc.y += v.y; acc.z += v.z; acc.w += v.w;
        }
        S[r * 132 + ng * 4 + 0] = fmaxf(acc.x, 0.f);
        S[r * 132 + ng * 4 + 1] = fmaxf(acc.y, 0.f);
        S[r * 132 + ng * 4 + 2] = fmaxf(acc.z, 0.f);
        S[r * 132 + ng * 4 + 3] = fmaxf(acc.w, 0.f);
        float4 h = *(const float4*)&g_states[(size_t)(r0 + r) * 192 + ng * 4];
        *(float4*)&S[r * 132 + 64 + ng * 4] = h;
    }
    for (int idx = tid; idx < 16384; idx += 256) {
        wS[(idx >> 6) * 130 + (idx & 63)]      = w1i[idx];
        wS[(idx >> 6) * 130 + 64 + (idx & 63)] = w1h[idx];
    }
    __syncthreads();
    ull wc[64];
#pragma unroll
    for (int k = 0; k < 64; k++) wc[k] = *(const ull*)&wS[tid * 130 + 2 * k];
    const float bias = g_b1c[tid];
    for (int r = 0; r < 16; r += 2) {
        ull a0 = pack2f(bias, 0.f), a1 = 0ull;
        ull c0 = pack2f(bias, 0.f), c1 = 0ull;
#pragma unroll
        for (int k = 0; k < 32; k++) {
            ffma2(a0, wc[2 * k],     *(const ull*)&S[r * 132 + 4 * k]);
            ffma2(a1, wc[2 * k + 1], *(const ull*)&S[r * 132 + 4 * k + 2]);
            ffma2(c0, wc[2 * k],     *(const ull*)&S[(r + 1) * 132 + 4 * k]);
            ffma2(c1, wc[2 * k + 1], *(const ull*)&S[(r + 1) * 132 + 4 * k + 2]);
        }
        float2 f0 = unpack2f(a0), f1 = unpack2f(a1);
        float2 g0 = unpack2f(c0), g1 = unpack2f(c1);
        g_XP[(size_t)(r0 + r) * 256 + tid]     = (f0.x + f0.y) + (f1.x + f1.y);
        g_XP[(size_t)(r0 + r + 1) * 256 + tid] = (g0.x + g0.y) + (g1.x + g1.y);
    }
}

// ---------------- LSTM scan: 12 warps, 1 gate-dot per thread, shfl cell, 1 bar/step ----------------
// warps 0-7: lstm1 (j = wid*8 + lane/4, gate q = lane&3, row = q*64+j)
// warps 8-11: lstm2 (j = (wid-8)*8 + lane/4, gate q = lane&3, row = q*32+j), pipelined at t-1
__global__ void __launch_bounds__(384, 1) scan_kernel() {
    __shared__ __align__(16) float h1s[2][64];
    __shared__ __align__(16) float h2s[2][32];
    const int tid = threadIdx.x;
    const int wid = tid >> 5, lane = tid & 31;
    const int b = blockIdx.x;
    const float* xp = g_XP + (size_t)b * 65536;
    float* st = g_states + (size_t)b * 49152;

    ull wreg[48];
    float bc2 = 0.f, cst = 0.f;
    const int q = lane & 3;
    int j, r;
    if (wid < 8) {
        j = (wid << 3) + (lane >> 2);
        r = (q << 6) + j;               // gate row = q*64 + j
#pragma unroll
        for (int k = 0; k < 32; k++) wreg[k] = g_w1hP[k * 256 + r];
    } else {
        j = ((wid - 8) << 3) + (lane >> 2);
        r = (q << 5) + j;               // gate row = q*32 + j
#pragma unroll
        for (int k = 0; k < 48; k++) wreg[k] = g_w2P[k * 128 + r];
        bc2 = g_b2c[r];
    }
    if (tid < 64) { h1s[0][tid] = 0.f; h1s[1][tid] = 0.f; }
    if (tid >= 64 && tid < 96) { h2s[0][tid - 64] = 0.f; h2s[1][tid - 64] = 0.f; }
    float xcur = 0.f, x1 = 0.f;
    if (wid < 8) { xcur = xp[r]; x1 = xp[256 + r]; }
    __syncthreads();

    for (int t = 0; t <= 256; t++) {
        const int buf = t & 1;
        if (wid < 8) {
            if (t < 256) {
                float x2 = 0.f;
                if (t + 2 < 256) x2 = xp[(t + 2) * 256 + r];
                const float* hb = h1s[buf];
                ull a0 = pack2f(xcur, 0.f), a1 = 0ull, a2 = 0ull, a3 = 0ull;
#pragma unroll
                for (int k = 0; k < 8; k++) {
                    ffma2(a0, wreg[4 * k + 0], *(const ull*)&hb[8 * k + 0]);
                    ffma2(a1, wreg[4 * k + 1], *(const ull*)&hb[8 * k + 2]);
                    ffma2(a2, wreg[4 * k + 2], *(const ull*)&hb[8 * k + 4]);
                    ffma2(a3, wreg[4 * k + 3], *(const ull*)&hb[8 * k + 6]);
                }
                float2 f0 = unpack2f(a0), f1 = unpack2f(a1);
                float2 f2 = unpack2f(a2), f3 = unpack2f(a3);
                float g = ((f0.x + f0.y) + (f1.x + f1.y)) + ((f2.x + f2.y) + (f3.x + f3.y));
                float act = (q == 2) ? tanh_f(g) : sig_f(g);
                const int base = lane & ~3;
                float fi = __shfl_sync(0xffffffffu, act, base + 0);
                float ff = __shfl_sync(0xffffffffu, act, base + 1);
                float fg = __shfl_sync(0xffffffffu, act, base + 2);
                float fo = __shfl_sync(0xffffffffu, act, base + 3);
                if (q == 0) {
                    float c = ff * cst + fi * fg;
                    float h = fo * tanh_f(c);
                    cst = c;
                    h1s[buf ^ 1][j] = h;
                    st[t * 192 + j] = h;
                    st[t * 192 + 64 + j] = c;
                }
                xcur = x1; x1 = x2;
            }
        } else if (t >= 1) {
            const int tp = t - 1;
            const float* hb1 = h1s[buf];
            const float* hb2 = h2s[buf];
            ull a0 = pack2f(bc2, 0.f), a1 = 0ull, a2 = 0ull, a3 = 0ull;
#pragma unroll
            for (int k = 0; k < 8; k++) {
                ffma2(a0, wreg[4 * k + 0], *(const ull*)&hb1[8 * k + 0]);
                ffma2(a1, wreg[4 * k + 1], *(const ull*)&hb1[8 * k + 2]);
                ffma2(a2, wreg[4 * k + 2], *(const ull*)&hb1[8 * k + 4]);
                ffma2(a3, wreg[4 * k + 3], *(const ull*)&hb1[8 * k + 6]);
            }
#pragma unroll
            for (int k = 0; k < 4; k++) {
                ffma2(a0, wreg[32 + 4 * k + 0], *(const ull*)&hb2[8 * k + 0]);
                ffma2(a1, wreg[32 + 4 * k + 1], *(const ull*)&hb2[8 * k + 2]);
                ffma2(a2, wreg[32 + 4 * k + 2], *(const ull*)&hb2[8 * k + 4]);
                ffma2(a3, wreg[32 + 4 * k + 3], *(const ull*)&hb2[8 * k + 6]);
            }
            float2 f0 = unpack2f(a0), f1 = unpack2f(a1);
            float2 f2 = unpack2f(a2), f3 = unpack2f(a3);
            float g = ((f0.x + f0.y) + (f1.x + f1.y)) + ((f2.x + f2.y) + (f3.x + f3.y));
            float act = (q == 2) ? tanh_f(g) : sig_f(g);
            const int base = lane & ~3;
            float fi = __shfl_sync(0xffffffffu, act, base + 0);
            float ff = __shfl_sync(0xffffffffu, act, base + 1);
            float fg = __shfl_sync(0xffffffffu, act, base + 2);
            float fo = __shfl_sync(0xffffffffu, act, base + 3);
            if (q == 0) {
                float c = ff * cst + fi * fg;
                float h = fo * tanh_f(c);
                cst = c;
                h2s[buf ^ 1][j] = h;
                st[tp * 192 + 128 + j] = h;
                st[tp * 192 + 160 + j] = c;
            }
        }
        __syncthreads();
    }
}

// ---------------- fused tail: flstm1 + gates2f + heads + fpool ----------------
__global__ void __launch_bounds__(128) tail_kernel(
        const float* __restrict__ fc8w, const float* __restrict__ fc8b,
        const float* __restrict__ fw, const float* __restrict__ fb,
        float* __restrict__ out, float* __restrict__ fpooled) {
    extern __shared__ float dsm[];
    float* wcS = dsm;               // [128][98]
    float* fwS = dsm + 128 * 98;    // [90][34]
    __shared__ float fh1[64], h2s[32], c2s[32], gs[128];
    const int tid = threadIdx.x;
    for (int idx = tid; idx < 12288; idx += 128)
        wcS[(idx / 96) * 98 + idx % 96] = g_Wcat2[idx];
    for (int idx = tid; idx < 2880; idx += 128)
        fwS[(idx >> 5) * 34 + (idx & 31)] = fw[idx];
    __syncthreads();
    float wcat[96];
#pragma unroll
    for (int k = 0; k < 96; k++) wcat[k] = wcS[tid * 98 + k];
    const float b2 = g_b2c[tid];
    const int po = tid - 32;
    float fwr[32];
    if (po >= 0 && po < 90) {
#pragma unroll
        for (int k = 0; k < 32; k++) fwr[k] = fwS[po * 34 + k];
    }
    const float w8 = (tid < 32) ? fc8w[tid] : 0.f;
    const float b8 = fc8b[0];
    const bool is_tanh2 = (tid >= 64 && tid < 96);

    for (int r = 0; r < 16; r++) {
        const int row = blockIdx.x * 16 + r;
        const float* xpf = g_XP + (size_t)row * 256;
        const float* st = g_states + (size_t)row * 192;
        if (tid < 64) {
            float i = sig_f(xpf[tid]);
            float f = sig_f(xpf[64 + tid]);
            float gg = tanh_f(xpf[128 + tid]);
            float o = sig_f(xpf[192 + tid]);
            float cn = f * st[64 + tid] + i * gg;
            fh1[tid] = o * tanh_f(cn);
        } else if (tid < 96) {
            h2s[tid - 64] = st[128 + (tid - 64)];
        } else {
            c2s[tid - 96] = st[160 + (tid - 96)];
        }
        __syncthreads();
        float a = b2;
#pragma unroll
        for (int k = 0; k < 64; k++) a += wcat[k] * fh1[k];
#pragma unroll
        for (int k = 0; k < 32; k++) a += wcat[64 + k] * h2s[k];
        gs[tid] = is_tanh2 ? tanh_f(a) : sig_f(a);
        __syncthreads();
        if (tid < 32) {
            float cn = gs[32 + tid] * c2s[tid] + gs[tid] * gs[64 + tid];
            float fh2 = gs[96 + tid] * tanh_f(cn);
            float v1 = h2s[tid] * w8;
            float v2 = fh2 * w8;
#pragma unroll
            for (int off = 16; off > 0; off >>= 1) {
                v1 += __shfl_down_sync(0xffffffffu, v1, off);
                v2 += __shfl_down_sync(0xffffffffu, v2, off);
            }
            if (tid == 0) {
                out[row] = sig_f(v1 + b8);
                out[NROWS + row] = sig_f(v2 + b8);
            }
        } else if (po < 90) {
            float s2 = fb[po];
#pragma unroll
            for (int k = 0; k < 32; k++) s2 += fwr[k] * h2s[k];
            fpooled[(size_t)row * 90 + po] = s2;
        }
        __syncthreads();
    }
}

// ---------------- host ----------------
extern "C" void kernel_launch(void* const* d_in, const int* in_sizes, int n_in,
                              void* d_out, int out_size) {
    const float* frames = (const float*)d_in[0];
    const float* spp_w  = (const float*)d_in[1];
    const float* spp_b  = (const float*)d_in[2];
    const float* fc7_w  = (const float*)d_in[3];
    const float* fc7_b  = (const float*)d_in[4];
    const float* w1i    = (const float*)d_in[5];
    const float* w1h    = (const float*)d_in[6];
    const float* b1i    = (const float*)d_in[7];
    const float* b1h    = (const float*)d_in[8];
    const float* w2i    = (const float*)d_in[9];
    const float* w2h    = (const float*)d_in[10];
    const float* b2i    = (const float*)d_in[11];
    const float* b2h    = (const float*)d_in[12];
    const float* fw     = (const float*)d_in[13];
    const float* fb     = (const float*)d_in[14];
    const float* fc8w   = (const float*)d_in[15];
    const float* fc8b   = (const float*)d_in[16];
    float* out = (float*)d_out;

    float *PART, *ST, *G, *CV;
    cudaGetSymbolAddress((void**)&PART, g_part);
    cudaGetSymbolAddress((void**)&ST, g_states);
    cudaGetSymbolAddress((void**)&G, g_G);
    cudaGetSymbolAddress((void**)&CV, g_cvec);

    const int SM1 = (128 * 90 + 32 * 90 + 64 * 36 + 128 * 40) * 4;
    const int SM2 = (128 * 34 + 32 * 34 + 64 * 36 + 128 * 40) * 4;
    const int SMRX = (256 * 66 + 16 * 66) * 4;
    const int SMRG = (256 * 130 + 16 * 132) * 4;
    const int SMT  = (128 * 98 + 90 * 34) * 4;
    cudaFuncSetAttribute(fused_mlp<90>, cudaFuncAttributeMaxDynamicSharedMemorySize, SM1);
    cudaFuncSetAttribute(fused_mlp<32>, cudaFuncAttributeMaxDynamicSharedMemorySize, SM2);
    cudaFuncSetAttribute(reduce_xp, cudaFuncAttributeMaxDynamicSharedMemorySize, SMRX);
    cudaFuncSetAttribute(reduce_gates, cudaFuncAttributeMaxDynamicSharedMemorySize, SMRG);
    cudaFuncSetAttribute(tail_kernel, cudaFuncAttributeMaxDynamicSharedMemorySize, SMT);

    float* pooled  = out + 2 * NROWS;
    float* fpooled = out + 2 * NROWS + NROWS * 90;

    spp_prep<<<6676, 256>>>(frames, pooled, spp_w, spp_b, fw, fb,
                            b1i, b1h, w1h, w2i, w2h, b2i, b2h);
    fused_mlp<90><<<dim3(SPLITS, 16), 256, SM1>>>(pooled, 90, spp_w, spp_b, fc7_w, PART);
    reduce_xp<<<128, 256, SMRX>>>(fc7_b, w1i);
    scan_kernel<<<8, 384>>>();
    fused_mlp<32><<<dim3(SPLITS, 16), 256, SM2>>>(ST + 128, 192, G, CV, fc7_w, PART);
    reduce_gates<<<128, 256, SMRG>>>(fc7_b, w1i, w1h);
    tail_kernel<<<128, 128, SMT>>>(fc8w, fc8b, fw, fb, out, fpooled);
}

// round 12
// speedup vs baseline: 1.3303x; 1.0064x over previous
#include <cuda_runtime.h>
#include <cuda_bf16.h>
#include <math.h>

#define NROWS 2048
#define EMBED 4096
#define SPLITS 16

typedef unsigned long long ull;

__device__ __forceinline__ void ffma2(ull& d, ull a, ull b) {
    asm("fma.rn.f32x2 %0, %1, %2, %3;" : "=l"(d) : "l"(a), "l"(b), "l"(d));
}
__device__ __forceinline__ ull pack2f(float x, float y) {
    ull r; asm("mov.b64 %0, {%1, %2};" : "=l"(r) : "f"(x), "f"(y)); return r;
}
__device__ __forceinline__ float2 unpack2f(ull v) {
    float2 f; asm("mov.b64 {%0, %1}, %2;" : "=f"(f.x), "=f"(f.y) : "l"(v)); return f;
}

// ---------------- scratch ----------------
__device__ float g_part[SPLITS * NROWS * 64];
__device__ float g_XP[NROWS * 256];
__device__ float g_states[NROWS * 192];   // per row: h1[64] c1[64] h2[32] c2[32]
__device__ float g_G[EMBED * 32];
__device__ float g_cvec[EMBED];
__device__ float g_Wcat2[128 * 96];
__device__ float g_b1c[256];
__device__ float g_b2c[128];
__device__ ull g_w1hP[32 * 256];          // k-major packed w1h rows
__device__ ull g_w2P[48 * 128];           // k-major packed [w2i|w2h] rows

__device__ __forceinline__ float sig_f(float x) {
    return __fdividef(1.0f, 1.0f + __expf(-x));
}
__device__ __forceinline__ float tanh_f(float x) {
    return __fdividef(2.0f, 1.0f + __expf(-2.0f * x)) - 1.0f;
}

// ---------------- merged SPP + prep ----------------
__global__ void spp_prep(const float* __restrict__ frames, float* __restrict__ pooled,
                         const float* __restrict__ spp_w, const float* __restrict__ spp_b,
                         const float* __restrict__ fw, const float* __restrict__ fb,
                         const float* __restrict__ b1i, const float* __restrict__ b1h,
                         const float* __restrict__ w1h,
                         const float* __restrict__ w2i, const float* __restrict__ w2h,
                         const float* __restrict__ b2i, const float* __restrict__ b2h) {
    const int tid = threadIdx.x;
    if (blockIdx.x < 6144) {
        __shared__ float tmax[144];
        const int nc = blockIdx.x;
        const int n = nc / 3, c = nc % 3;
        const float* img = frames + (size_t)nc * 9216;
        if (tid < 144) {
            const int ti = tid / 12, tj = tid % 12;
            const float* p = img + ti * 8 * 96 + tj * 8;
            float m = -3.402823466e38f;
#pragma unroll
            for (int r = 0; r < 8; r++) {
                float4 v0 = *(const float4*)(p + r * 96);
                float4 v1 = *(const float4*)(p + r * 96 + 4);
                m = fmaxf(m, fmaxf(fmaxf(v0.x, v0.y), fmaxf(v0.z, v0.w)));
                m = fmaxf(m, fmaxf(fmaxf(v1.x, v1.y), fmaxf(v1.z, v1.w)));
            }
            tmax[tid] = m;
        }
        __syncthreads();
        float* orow = pooled + (size_t)n * 90;
        if (tid < 16) {
            int i = tid / 4, j = tid % 4;
            float m = -3.402823466e38f;
            for (int a = 0; a < 3; a++) for (int b = 0; b < 3; b++)
                m = fmaxf(m, tmax[(i * 3 + a) * 12 + (j * 3 + b)]);
            orow[c * 16 + i * 4 + j] = m;
        } else if (tid < 25) {
            int q = tid - 16, i = q / 3, j = q % 3;
            float m = -3.402823466e38f;
            for (int a = 0; a < 4; a++) for (int b = 0; b < 4; b++)
                m = fmaxf(m, tmax[(i * 4 + a) * 12 + (j * 4 + b)]);
            orow[48 + c * 9 + i * 3 + j] = m;
        } else if (tid < 29) {
            int q = tid - 25, i = q / 2, j = q % 2;
            float m = -3.402823466e38f;
            for (int a = 0; a < 6; a++) for (int b = 0; b < 6; b++)
                m = fmaxf(m, tmax[(i * 6 + a) * 12 + (j * 6 + b)]);
            orow[75 + c * 4 + i * 2 + j] = m;
        } else if (tid == 29) {
            float m = -3.402823466e38f;
            for (int a = 0; a < 144; a++) m = fmaxf(m, tmax[a]);
            orow[87 + c] = m;
        }
        return;
    }
    const int blk = blockIdx.x - 6144;
    if (blk < 512) {
        int o = blk * 256 + tid;
        int i = o >> 5, j = o & 31;
        float s = 0.f;
        for (int p = 0; p < 90; p++) s += spp_w[i * 90 + p] * fw[p * 32 + j];
        g_G[o] = s;
    } else if (blk < 528) {
        int i = (blk - 512) * 256 + tid;
        float s = spp_b[i];
        for (int p = 0; p < 90; p++) s += spp_w[i * 90 + p] * fb[p];
        g_cvec[i] = s;
    } else if (blk == 528) {
        g_b1c[tid] = b1i[tid] + b1h[tid];
        if (tid < 128) g_b2c[tid] = b2i[tid] + b2h[tid];
    } else if (blk == 529) {
        for (int idx = tid; idx < 12288; idx += 256) {
            int g = idx / 96, k = idx - g * 96;
            g_Wcat2[idx] = (k < 64) ? w2i[g * 64 + k] : w2h[g * 32 + (k - 64)];
        }
    } else if (blk == 530) {
        for (int idx = tid; idx < 8192; idx += 256) {
            int k = idx >> 8, r = idx & 255;
            g_w1hP[idx] = pack2f(w1h[r * 64 + 2 * k], w1h[r * 64 + 2 * k + 1]);
        }
    } else if (blk == 531) {
        for (int idx = tid; idx < 6144; idx += 256) {
            int k = idx >> 7, r = idx & 127;
            ull v;
            if (k < 32) v = pack2f(w2i[r * 64 + 2 * k], w2i[r * 64 + 2 * k + 1]);
            else { int k2 = k - 32; v = pack2f(w2h[r * 32 + 2 * k2], w2h[r * 32 + 2 * k2 + 1]); }
            g_w2P[idx] = v;
        }
    }
}

// ---------------- fused two-layer MLP (proven 128-row tile) ----------------
template<int KA>
__global__ void __launch_bounds__(256) fused_mlp(
        const float* __restrict__ A, int lda,
        const float* __restrict__ W1, const float* __restrict__ b1,
        const float* __restrict__ fc7, float* __restrict__ part) {
    constexpr int KAP = (KA == 90) ? 90 : 34;
    constexpr int WS  = KAP;
    constexpr int NW  = (32 * KA + 255) / 256;
    extern __shared__ float sm[];
    float* A2 = sm;                       // [128][KAP]
    float* W2 = A2 + 128 * KAP;           // [32][WS]
    float* F2 = W2 + 32 * WS;             // [64][36] swizzled
    float* Es = F2 + 64 * 36;             // [128][40] swizzled
    const int tid = threadIdx.x;
    const int s = blockIdx.x, m0 = blockIdx.y * 128;
    for (int idx = tid; idx < 128 * KA; idx += 256) {
        int r = idx / KA, p = idx - r * KA;
        A2[r * KAP + p] = A[(size_t)(m0 + r) * lda + p];
    }
    ull acc2[8][4];
#pragma unroll
    for (int i = 0; i < 8; i++)
#pragma unroll
        for (int j = 0; j < 4; j++) acc2[i][j] = 0ull;
    const int kbase = s * 256;
    const int txE = tid & 7, tyE = tid >> 3;
    const int txM = tid & 15, tyM = tid >> 4;
    const int eswM = 4 * (tyM & 7);
    const int fswM = 4 * (txM & 7);

    float pw[NW], pf[8];
#pragma unroll
    for (int i = 0; i < NW; i++) {
        int idx = tid + i * 256;
        if (idx < 32 * KA) pw[i] = W1[(size_t)(kbase + idx / KA) * KA + idx % KA];
    }
#pragma unroll
    for (int i = 0; i < 8; i++) {
        int idx = tid + i * 256;
        pf[i] = fc7[(size_t)(idx >> 5) * 4096 + kbase + (idx & 31)];
    }

    for (int kc = 0; kc < 256; kc += 32) {
        const int cg0 = kbase + kc;
        __syncthreads();
#pragma unroll
        for (int i = 0; i < NW; i++) {
            int idx = tid + i * 256;
            if (idx < 32 * KA) W2[(idx / KA) * WS + idx % KA] = pw[i];
        }
#pragma unroll
        for (int i = 0; i < 8; i++) {
            int idx = tid + i * 256;
            int n = idx >> 5, kk = idx & 31;
            F2[n * 36 + (kk ^ (4 * ((n >> 2) & 7)))] = pf[i];
        }
        __syncthreads();
        if (kc + 32 < 256) {
            const int ng0 = cg0 + 32;
#pragma unroll
            for (int i = 0; i < NW; i++) {
                int idx = tid + i * 256;
                if (idx < 32 * KA) pw[i] = W1[(size_t)(ng0 + idx / KA) * KA + idx % KA];
            }
#pragma unroll
            for (int i = 0; i < 8; i++) {
                int idx = tid + i * 256;
                pf[i] = fc7[(size_t)(idx >> 5) * 4096 + ng0 + (idx & 31)];
            }
        }
        ull e2[4][4];
#pragma unroll
        for (int i = 0; i < 4; i++)
#pragma unroll
            for (int j = 0; j < 4; j++) e2[i][j] = 0ull;
#pragma unroll 15
        for (int p = 0; p < KA; p += 2) {
            ull a0 = *(const ull*)&A2[(tyE * 4 + 0) * KAP + p];
            ull a1 = *(const ull*)&A2[(tyE * 4 + 1) * KAP + p];
            ull a2 = *(const ull*)&A2[(tyE * 4 + 2) * KAP + p];
            ull a3 = *(const ull*)&A2[(tyE * 4 + 3) * KAP + p];
            ull w0 = *(const ull*)&W2[(txE * 4 + 0) * WS + p];
            ull w1 = *(const ull*)&W2[(txE * 4 + 1) * WS + p];
            ull w2 = *(const ull*)&W2[(txE * 4 + 2) * WS + p];
            ull w3 = *(const ull*)&W2[(txE * 4 + 3) * WS + p];
            ffma2(e2[0][0], a0, w0); ffma2(e2[0][1], a0, w1);
            ffma2(e2[0][2], a0, w2); ffma2(e2[0][3], a0, w3);
            ffma2(e2[1][0], a1, w0); ffma2(e2[1][1], a1, w1);
            ffma2(e2[1][2], a1, w2); ffma2(e2[1][3], a1, w3);
            ffma2(e2[2][0], a2, w0); ffma2(e2[2][1], a2, w1);
            ffma2(e2[2][2], a2, w2); ffma2(e2[2][3], a2, w3);
            ffma2(e2[3][0], a3, w0); ffma2(e2[3][1], a3, w1);
            ffma2(e2[3][2], a3, w2); ffma2(e2[3][3], a3, w3);
        }
#pragma unroll
        for (int i = 0; i < 4; i++) {
            int r = tyE * 4 + i;
            int swz = 4 * ((r >> 3) & 7);
#pragma unroll
            for (int j = 0; j < 4; j++) {
                int c = txE * 4 + j;
                float2 f = unpack2f(e2[i][j]);
                float v = f.x + f.y + b1[cg0 + c];
                Es[r * 40 + (c ^ swz)] = fmaxf(v, 0.f);
            }
        }
        __syncthreads();
#pragma unroll
        for (int kk = 0; kk < 32; kk += 2) {
            ull e[8], fv[4];
#pragma unroll
            for (int i = 0; i < 8; i++)
                e[i] = *(const ull*)&Es[(tyM * 8 + i) * 40 + (kk ^ eswM)];
#pragma unroll
            for (int j = 0; j < 4; j++)
                fv[j] = *(const ull*)&F2[(txM * 4 + j) * 36 + (kk ^ fswM)];
#pragma unroll
            for (int i = 0; i < 8; i++)
#pragma unroll
                for (int j = 0; j < 4; j++) ffma2(acc2[i][j], e[i], fv[j]);
        }
    }
#pragma unroll
    for (int i = 0; i < 8; i++)
#pragma unroll
        for (int j = 0; j < 4; j++) {
            float2 f = unpack2f(acc2[i][j]);
            part[((size_t)s * NROWS + m0 + tyM * 8 + i) * 64 + txM * 4 + j] = f.x + f.y;
        }
}

// ---------------- reduce partials -> emb, then XP = emb@w1i^T + b1c ----------------
__global__ void __launch_bounds__(256) reduce_xp(const float* __restrict__ fc7_b,
                                                 const float* __restrict__ w1i) {
    extern __shared__ float dsm[];
    float* wS   = dsm;              // [256][66]
    float* embS = dsm + 256 * 66;   // [16][66]
    const int tid = threadIdx.x;
    const int r0 = blockIdx.x * 16;
    {
        int r = tid >> 4, ng = tid & 15;
        float4 acc = *(const float4*)&fc7_b[ng * 4];
#pragma unroll
        for (int ss = 0; ss < SPLITS; ss++) {
            float4 v = *(const float4*)&g_part[((size_t)ss * NROWS + r0 + r) * 64 + ng * 4];
            acc.x += v.x; acc.y += v.y; acc.z += v.z; acc.w += v.w;
        }
        embS[r * 66 + ng * 4 + 0] = fmaxf(acc.x, 0.f);
        embS[r * 66 + ng * 4 + 1] = fmaxf(acc.y, 0.f);
        embS[r * 66 + ng * 4 + 2] = fmaxf(acc.z, 0.f);
        embS[r * 66 + ng * 4 + 3] = fmaxf(acc.w, 0.f);
    }
    for (int idx = tid; idx < 16384; idx += 256)
        wS[(idx >> 6) * 66 + (idx & 63)] = w1i[idx];
    __syncthreads();
    ull w[32];
#pragma unroll
    for (int k = 0; k < 32; k++) w[k] = *(const ull*)&wS[tid * 66 + 2 * k];
    const float bias = g_b1c[tid];
    for (int r = 0; r < 16; r += 2) {
        ull a0 = pack2f(bias, 0.f), a1 = 0ull;
        ull c0 = pack2f(bias, 0.f), c1 = 0ull;
#pragma unroll
        for (int k = 0; k < 16; k++) {
            ffma2(a0, w[2 * k],     *(const ull*)&embS[r * 66 + 4 * k]);
            ffma2(a1, w[2 * k + 1], *(const ull*)&embS[r * 66 + 4 * k + 2]);
            ffma2(c0, w[2 * k],     *(const ull*)&embS[(r + 1) * 66 + 4 * k]);
            ffma2(c1, w[2 * k + 1], *(const ull*)&embS[(r + 1) * 66 + 4 * k + 2]);
        }
        float2 f0 = unpack2f(a0), f1 = unpack2f(a1);
        float2 g0 = unpack2f(c0), g1 = unpack2f(c1);
        g_XP[(size_t)(r0 + r) * 256 + tid]     = (f0.x + f0.y) + (f1.x + f1.y);
        g_XP[(size_t)(r0 + r + 1) * 256 + tid] = (g0.x + g0.y) + (g1.x + g1.y);
    }
}

// ---------------- reduce fe partials; gates1f = [fe|h1]@[w1i|w1h]^T + b1c -> g_XP ----------------
__global__ void __launch_bounds__(256) reduce_gates(const float* __restrict__ fc7_b,
                                                    const float* __restrict__ w1i,
                                                    const float* __restrict__ w1h) {
    extern __shared__ float dsm[];
    float* wS = dsm;                // [256][130]
    float* S  = dsm + 256 * 130;    // [16][132]
    const int tid = threadIdx.x;
    const int r0 = blockIdx.x * 16;
    {
        int r = tid >> 4, ng = tid & 15;
        float4 acc = *(const float4*)&fc7_b[ng * 4];
#pragma unroll
        for (int ss = 0; ss < SPLITS; ss++) {
            float4 v = *(const float4*)&g_part[((size_t)ss * NROWS + r0 + r) * 64 + ng * 4];
            acc.x += v.x; acc.y += v.y; acc.z += v.z; acc.w += v.w;
        }
        S[r * 132 + ng * 4 + 0] = fmaxf(acc.x, 0.f);
        S[r * 132 + ng * 4 + 1] = fmaxf(acc.y, 0.f);
        S[r * 132 + ng * 4 + 2] = fmaxf(acc.z, 0.f);
        S[r * 132 + ng * 4 + 3] = fmaxf(acc.w, 0.f);
        float4 h = *(const float4*)&g_states[(size_t)(r0 + r) * 192 + ng * 4];
        *(float4*)&S[r * 132 + 64 + ng * 4] = h;
    }
    for (int idx = tid; idx < 16384; idx += 256) {
        wS[(idx >> 6) * 130 + (idx & 63)]      = w1i[idx];
        wS[(idx >> 6) * 130 + 64 + (idx & 63)] = w1h[idx];
    }
    __syncthreads();
    ull wc[64];
#pragma unroll
    for (int k = 0; k < 64; k++) wc[k] = *(const ull*)&wS[tid * 130 + 2 * k];
    const float bias = g_b1c[tid];
    for (int r = 0; r < 16; r += 2) {
        ull a0 = pack2f(bias, 0.f), a1 = 0ull;
        ull c0 = pack2f(bias, 0.f), c1 = 0ull;
#pragma unroll
        for (int k = 0; k < 32; k++) {
            ffma2(a0, wc[2 * k],     *(const ull*)&S[r * 132 + 4 * k]);
            ffma2(a1, wc[2 * k + 1], *(const ull*)&S[r * 132 + 4 * k + 2]);
            ffma2(c0, wc[2 * k],     *(const ull*)&S[(r + 1) * 132 + 4 * k]);
            ffma2(c1, wc[2 * k + 1], *(const ull*)&S[(r + 1) * 132 + 4 * k + 2]);
        }
        float2 f0 = unpack2f(a0), f1 = unpack2f(a1);
        float2 g0 = unpack2f(c0), g1 = unpack2f(c1);
        g_XP[(size_t)(r0 + r) * 256 + tid]     = (f0.x + f0.y) + (f1.x + f1.y);
        g_XP[(size_t)(r0 + r + 1) * 256 + tid] = (g0.x + g0.y) + (g1.x + g1.y);
    }
}

// ---------------- LSTM scan: 12 warps, 1 gate-dot/thread, shfl cell, 1 bar/step ----------------
// h reads via 128-bit broadcast LDS (ulonglong2) — halves LDS issue count vs scalar ull loads.
__global__ void __launch_bounds__(384, 1) scan_kernel() {
    __shared__ __align__(16) float h1s[2][64];
    __shared__ __align__(16) float h2s[2][32];
    const int tid = threadIdx.x;
    const int wid = tid >> 5, lane = tid & 31;
    const int b = blockIdx.x;
    const float* xp = g_XP + (size_t)b * 65536;
    float* st = g_states + (size_t)b * 49152;

    ull wreg[48];
    float bc2 = 0.f, cst = 0.f;
    const int q = lane & 3;
    int j, r;
    if (wid < 8) {
        j = (wid << 3) + (lane >> 2);
        r = (q << 6) + j;               // gate row = q*64 + j
#pragma unroll
        for (int k = 0; k < 32; k++) wreg[k] = g_w1hP[k * 256 + r];
    } else {
        j = ((wid - 8) << 3) + (lane >> 2);
        r = (q << 5) + j;               // gate row = q*32 + j
#pragma unroll
        for (int k = 0; k < 48; k++) wreg[k] = g_w2P[k * 128 + r];
        bc2 = g_b2c[r];
    }
    if (tid < 64) { h1s[0][tid] = 0.f; h1s[1][tid] = 0.f; }
    if (tid >= 64 && tid < 96) { h2s[0][tid - 64] = 0.f; h2s[1][tid - 64] = 0.f; }
    float xcur = 0.f, x1 = 0.f;
    if (wid < 8) { xcur = xp[r]; x1 = xp[256 + r]; }
    __syncthreads();

    for (int t = 0; t <= 256; t++) {
        const int buf = t & 1;
        if (wid < 8) {
            if (t < 256) {
                float x2 = 0.f;
                if (t + 2 < 256) x2 = xp[(t + 2) * 256 + r];
                const float* hb = h1s[buf];
                ull a0 = pack2f(xcur, 0.f), a1 = 0ull, a2 = 0ull, a3 = 0ull;
#pragma unroll
                for (int k = 0; k < 8; k++) {
                    ulonglong2 hA = *(const ulonglong2*)&hb[8 * k + 0];
                    ulonglong2 hB = *(const ulonglong2*)&hb[8 * k + 4];
                    ffma2(a0, wreg[4 * k + 0], hA.x);
                    ffma2(a1, wreg[4 * k + 1], hA.y);
                    ffma2(a2, wreg[4 * k + 2], hB.x);
                    ffma2(a3, wreg[4 * k + 3], hB.y);
                }
                float2 f0 = unpack2f(a0), f1 = unpack2f(a1);
                float2 f2 = unpack2f(a2), f3 = unpack2f(a3);
                float g = ((f0.x + f0.y) + (f1.x + f1.y)) + ((f2.x + f2.y) + (f3.x + f3.y));
                float act = (q == 2) ? tanh_f(g) : sig_f(g);
                const int base = lane & ~3;
                float fi = __shfl_sync(0xffffffffu, act, base + 0);
                float ff = __shfl_sync(0xffffffffu, act, base + 1);
                float fg = __shfl_sync(0xffffffffu, act, base + 2);
                float fo = __shfl_sync(0xffffffffu, act, base + 3);
                if (q == 0) {
                    float c = ff * cst + fi * fg;
                    float h = fo * tanh_f(c);
                    cst = c;
                    h1s[buf ^ 1][j] = h;
                    st[t * 192 + j] = h;
                    st[t * 192 + 64 + j] = c;
                }
                xcur = x1; x1 = x2;
            }
        } else if (t >= 1) {
            const int tp = t - 1;
            const float* hb1 = h1s[buf];
            const float* hb2 = h2s[buf];
            ull a0 = pack2f(bc2, 0.f), a1 = 0ull, a2 = 0ull, a3 = 0ull;
#pragma unroll
            for (int k = 0; k < 8; k++) {
                ulonglong2 hA = *(const ulonglong2*)&hb1[8 * k + 0];
                ulonglong2 hB = *(const ulonglong2*)&hb1[8 * k + 4];
                ffma2(a0, wreg[4 * k + 0], hA.x);
                ffma2(a1, wreg[4 * k + 1], hA.y);
                ffma2(a2, wreg[4 * k + 2], hB.x);
                ffma2(a3, wreg[4 * k + 3], hB.y);
            }
#pragma unroll
            for (int k = 0; k < 4; k++) {
                ulonglong2 hA = *(const ulonglong2*)&hb2[8 * k + 0];
                ulonglong2 hB = *(const ulonglong2*)&hb2[8 * k + 4];
                ffma2(a0, wreg[32 + 4 * k + 0], hA.x);
                ffma2(a1, wreg[32 + 4 * k + 1], hA.y);
                ffma2(a2, wreg[32 + 4 * k + 2], hB.x);
                ffma2(a3, wreg[32 + 4 * k + 3], hB.y);
            }
            float2 f0 = unpack2f(a0), f1 = unpack2f(a1);
            float2 f2 = unpack2f(a2), f3 = unpack2f(a3);
            float g = ((f0.x + f0.y) + (f1.x + f1.y)) + ((f2.x + f2.y) + (f3.x + f3.y));
            float act = (q == 2) ? tanh_f(g) : sig_f(g);
            const int base = lane & ~3;
            float fi = __shfl_sync(0xffffffffu, act, base + 0);
            float ff = __shfl_sync(0xffffffffu, act, base + 1);
            float fg = __shfl_sync(0xffffffffu, act, base + 2);
            float fo = __shfl_sync(0xffffffffu, act, base + 3);
            if (q == 0) {
                float c = ff * cst + fi * fg;
                float h = fo * tanh_f(c);
                cst = c;
                h2s[buf ^ 1][j] = h;
                st[tp * 192 + 128 + j] = h;
                st[tp * 192 + 160 + j] = c;
            }
        }
        __syncthreads();
    }
}

// ---------------- fused tail: flstm1 + gates2f + heads + fpool ----------------
__global__ void __launch_bounds__(128) tail_kernel(
        const float* __restrict__ fc8w, const float* __restrict__ fc8b,
        const float* __restrict__ fw, const float* __restrict__ fb,
        float* __restrict__ out, float* __restrict__ fpooled) {
    extern __shared__ float dsm[];
    float* wcS = dsm;               // [128][98]
    float* fwS = dsm + 128 * 98;    // [90][34]
    __shared__ float fh1[64], h2s[32], c2s[32], gs[128];
    const int tid = threadIdx.x;
    for (int idx = tid; idx < 12288; idx += 128)
        wcS[(idx / 96) * 98 + idx % 96] = g_Wcat2[idx];
    for (int idx = tid; idx < 2880; idx += 128)
        fwS[(idx >> 5) * 34 + (idx & 31)] = fw[idx];
    __syncthreads();
    float wcat[96];
#pragma unroll
    for (int k = 0; k < 96; k++) wcat[k] = wcS[tid * 98 + k];
    const float b2 = g_b2c[tid];
    const int po = tid - 32;
    float fwr[32];
    if (po >= 0 && po < 90) {
#pragma unroll
        for (int k = 0; k < 32; k++) fwr[k] = fwS[po * 34 + k];
    }
    const float w8 = (tid < 32) ? fc8w[tid] : 0.f;
    const float b8 = fc8b[0];
    const bool is_tanh2 = (tid >= 64 && tid < 96);

    for (int r = 0; r < 16; r++) {
        const int row = blockIdx.x * 16 + r;
        const float* xpf = g_XP + (size_t)row * 256;
        const float* st = g_states + (size_t)row * 192;
        if (tid < 64) {
            float i = sig_f(xpf[tid]);
            float f = sig_f(xpf[64 + tid]);
            float gg = tanh_f(xpf[128 + tid]);
            float o = sig_f(xpf[192 + tid]);
            float cn = f * st[64 + tid] + i * gg;
            fh1[tid] = o * tanh_f(cn);
        } else if (tid < 96) {
            h2s[tid - 64] = st[128 + (tid - 64)];
        } else {
            c2s[tid - 96] = st[160 + (tid - 96)];
        }
        __syncthreads();
        float a = b2;
#pragma unroll
        for (int k = 0; k < 64; k++) a += wcat[k] * fh1[k];
#pragma unroll
        for (int k = 0; k < 32; k++) a += wcat[64 + k] * h2s[k];
        gs[tid] = is_tanh2 ? tanh_f(a) : sig_f(a);
        __syncthreads();
        if (tid < 32) {
            float cn = gs[32 + tid] * c2s[tid] + gs[tid] * gs[64 + tid];
            float fh2 = gs[96 + tid] * tanh_f(cn);
            float v1 = h2s[tid] * w8;
            float v2 = fh2 * w8;
#pragma unroll
            for (int off = 16; off > 0; off >>= 1) {
                v1 += __shfl_down_sync(0xffffffffu, v1, off);
                v2 += __shfl_down_sync(0xffffffffu, v2, off);
            }
            if (tid == 0) {
                out[row] = sig_f(v1 + b8);
                out[NROWS + row] = sig_f(v2 + b8);
            }
        } else if (po < 90) {
            float s2 = fb[po];
#pragma unroll
            for (int k = 0; k < 32; k++) s2 += fwr[k] * h2s[k];
            fpooled[(size_t)row * 90 + po] = s2;
        }
        __syncthreads();
    }
}

// ---------------- host ----------------
extern "C" void kernel_launch(void* const* d_in, const int* in_sizes, int n_in,
                              void* d_out, int out_size) {
    const float* frames = (const float*)d_in[0];
    const float* spp_w  = (const float*)d_in[1];
    const float* spp_b  = (const float*)d_in[2];
    const float* fc7_w  = (const float*)d_in[3];
    const float* fc7_b  = (const float*)d_in[4];
    const float* w1i    = (const float*)d_in[5];
    const float* w1h    = (const float*)d_in[6];
    const float* b1i    = (const float*)d_in[7];
    const float* b1h    = (const float*)d_in[8];
    const float* w2i    = (const float*)d_in[9];
    const float* w2h    = (const float*)d_in[10];
    const float* b2i    = (const float*)d_in[11];
    const float* b2h    = (const float*)d_in[12];
    const float* fw     = (const float*)d_in[13];
    const float* fb     = (const float*)d_in[14];
    const float* fc8w   = (const float*)d_in[15];
    const float* fc8b   = (const float*)d_in[16];
    float* out = (float*)d_out;

    float *PART, *ST, *G, *CV;
    cudaGetSymbolAddress((void**)&PART, g_part);
    cudaGetSymbolAddress((void**)&ST, g_states);
    cudaGetSymbolAddress((void**)&G, g_G);
    cudaGetSymbolAddress((void**)&CV, g_cvec);

    const int SM1 = (128 * 90 + 32 * 90 + 64 * 36 + 128 * 40) * 4;
    const int SM2 = (128 * 34 + 32 * 34 + 64 * 36 + 128 * 40) * 4;
    const int SMRX = (256 * 66 + 16 * 66) * 4;
    const int SMRG = (256 * 130 + 16 * 132) * 4;
    const int SMT  = (128 * 98 + 90 * 34) * 4;
    cudaFuncSetAttribute(fused_mlp<90>, cudaFuncAttributeMaxDynamicSharedMemorySize, SM1);
    cudaFuncSetAttribute(fused_mlp<32>, cudaFuncAttributeMaxDynamicSharedMemorySize, SM2);
    cudaFuncSetAttribute(reduce_xp, cudaFuncAttributeMaxDynamicSharedMemorySize, SMRX);
    cudaFuncSetAttribute(reduce_gates, cudaFuncAttributeMaxDynamicSharedMemorySize, SMRG);
    cudaFuncSetAttribute(tail_kernel, cudaFuncAttributeMaxDynamicSharedMemorySize, SMT);

    float* pooled  = out + 2 * NROWS;
    float* fpooled = out + 2 * NROWS + NROWS * 90;

    spp_prep<<<6676, 256>>>(frames, pooled, spp_w, spp_b, fw, fb,
                            b1i, b1h, w1h, w2i, w2h, b2i, b2h);
    fused_mlp<90><<<dim3(SPLITS, 16), 256, SM1>>>(pooled, 90, spp_w, spp_b, fc7_w, PART);
    reduce_xp<<<128, 256, SMRX>>>(fc7_b, w1i);
    scan_kernel<<<8, 384>>>();
    fused_mlp<32><<<dim3(SPLITS, 16), 256, SM2>>>(ST + 128, 192, G, CV, fc7_w, PART);
    reduce_gates<<<128, 256, SMRG>>>(fc7_b, w1i, w1h);
    tail_kernel<<<128, 128, SMT>>>(fc8w, fc8b, fw, fb, out, fpooled);
}

// round 13
// speedup vs baseline: 1.4672x; 1.1029x over previous
#include <cuda_runtime.h>
#include <cuda_bf16.h>
#include <math.h>

#define NROWS 2048
#define EMBED 4096
#define SPLITS 16

typedef unsigned long long ull;

__device__ __forceinline__ void ffma2(ull& d, ull a, ull b) {
    asm("fma.rn.f32x2 %0, %1, %2, %3;" : "=l"(d) : "l"(a), "l"(b), "l"(d));
}
__device__ __forceinline__ ull pack2f(float x, float y) {
    ull r; asm("mov.b64 %0, {%1, %2};" : "=l"(r) : "f"(x), "f"(y)); return r;
}
__device__ __forceinline__ float2 unpack2f(ull v) {
    float2 f; asm("mov.b64 {%0, %1}, %2;" : "=f"(f.x), "=f"(f.y) : "l"(v)); return f;
}
__device__ __forceinline__ int ld_acq(const int* p) {
    int v; asm volatile("ld.acquire.gpu.global.b32 %0, [%1];" : "=r"(v) : "l"(p)); return v;
}
__device__ __forceinline__ void st_rel(int* p, int v) {
    asm volatile("st.release.gpu.global.b32 [%0], %1;" :: "l"(p), "r"(v));
}

// ---------------- scratch ----------------
__device__ float g_part[SPLITS * NROWS * 64];
__device__ float g_XP[NROWS * 256];
__device__ float g_states[NROWS * 192];   // per row: h1[64] c1[64] h2[32] c2[32]
__device__ float g_G[EMBED * 32];
__device__ float g_cvec[EMBED];
__device__ float g_b1c[256];
__device__ float g_b2c[128];
__device__ ull g_w1hP[32 * 256];          // k-major packed w1h rows
__device__ ull g_w2P[48 * 128];           // k-major packed [w2i|w2h] rows
__device__ ull g_wc1P[64 * 256];          // k-major packed [w1i|w1h] rows (gates1f)
__device__ float g_wc2Pf[96 * 128];       // k-major packed [w2i|w2h] float (gates2f)
// flags
__device__ int g_prog[8];
__device__ int g_done32[16];
__device__ int g_doneRG[128];

__device__ __forceinline__ float sig_f(float x) {
    return __fdividef(1.0f, 1.0f + __expf(-x));
}
__device__ __forceinline__ float tanh_f(float x) {
    return __fdividef(2.0f, 1.0f + __expf(-2.0f * x)) - 1.0f;
}

// ---------------- merged SPP + prep ----------------
__global__ void spp_prep(const float* __restrict__ frames, float* __restrict__ pooled,
                         const float* __restrict__ spp_w, const float* __restrict__ spp_b,
                         const float* __restrict__ fw, const float* __restrict__ fb,
                         const float* __restrict__ b1i, const float* __restrict__ b1h,
                         const float* __restrict__ w1i, const float* __restrict__ w1h,
                         const float* __restrict__ w2i, const float* __restrict__ w2h,
                         const float* __restrict__ b2i, const float* __restrict__ b2h) {
    const int tid = threadIdx.x;
    if (blockIdx.x < 6144) {
        __shared__ float tmax[144];
        const int nc = blockIdx.x;
        const int n = nc / 3, c = nc % 3;
        const float* img = frames + (size_t)nc * 9216;
        if (tid < 144) {
            const int ti = tid / 12, tj = tid % 12;
            const float* p = img + ti * 8 * 96 + tj * 8;
            float m = -3.402823466e38f;
#pragma unroll
            for (int r = 0; r < 8; r++) {
                float4 v0 = *(const float4*)(p + r * 96);
                float4 v1 = *(const float4*)(p + r * 96 + 4);
                m = fmaxf(m, fmaxf(fmaxf(v0.x, v0.y), fmaxf(v0.z, v0.w)));
                m = fmaxf(m, fmaxf(fmaxf(v1.x, v1.y), fmaxf(v1.z, v1.w)));
            }
            tmax[tid] = m;
        }
        __syncthreads();
        float* orow = pooled + (size_t)n * 90;
        if (tid < 16) {
            int i = tid / 4, j = tid % 4;
            float m = -3.402823466e38f;
            for (int a = 0; a < 3; a++) for (int b = 0; b < 3; b++)
                m = fmaxf(m, tmax[(i * 3 + a) * 12 + (j * 3 + b)]);
            orow[c * 16 + i * 4 + j] = m;
        } else if (tid < 25) {
            int q = tid - 16, i = q / 3, j = q % 3;
            float m = -3.402823466e38f;
            for (int a = 0; a < 4; a++) for (int b = 0; b < 4; b++)
                m = fmaxf(m, tmax[(i * 4 + a) * 12 + (j * 4 + b)]);
            orow[48 + c * 9 + i * 3 + j] = m;
        } else if (tid < 29) {
            int q = tid - 25, i = q / 2, j = q % 2;
            float m = -3.402823466e38f;
            for (int a = 0; a < 6; a++) for (int b = 0; b < 6; b++)
                m = fmaxf(m, tmax[(i * 6 + a) * 12 + (j * 6 + b)]);
            orow[75 + c * 4 + i * 2 + j] = m;
        } else if (tid == 29) {
            float m = -3.402823466e38f;
            for (int a = 0; a < 144; a++) m = fmaxf(m, tmax[a]);
            orow[87 + c] = m;
        }
        return;
    }
    const int blk = blockIdx.x - 6144;
    if (blk < 512) {
        int o = blk * 256 + tid;
        int i = o >> 5, j = o & 31;
        float s = 0.f;
        for (int p = 0; p < 90; p++) s += spp_w[i * 90 + p] * fw[p * 32 + j];
        g_G[o] = s;
    } else if (blk < 528) {
        int i = (blk - 512) * 256 + tid;
        float s = spp_b[i];
        for (int p = 0; p < 90; p++) s += spp_w[i * 90 + p] * fb[p];
        g_cvec[i] = s;
    } else if (blk == 528) {
        g_b1c[tid] = b1i[tid] + b1h[tid];
        if (tid < 128) g_b2c[tid] = b2i[tid] + b2h[tid];
        if (tid < 8) g_prog[tid] = 0;
        if (tid < 16) g_done32[tid] = 0;
        if (tid < 128) g_doneRG[tid] = 0;
    } else if (blk == 529) {
        for (int idx = tid; idx < 8192; idx += 256) {
            int k = idx >> 8, r = idx & 255;
            g_w1hP[idx] = pack2f(w1h[r * 64 + 2 * k], w1h[r * 64 + 2 * k + 1]);
        }
    } else if (blk == 530) {
        for (int idx = tid; idx < 6144; idx += 256) {
            int k = idx >> 7, r = idx & 127;
            ull v;
            if (k < 32) v = pack2f(w2i[r * 64 + 2 * k], w2i[r * 64 + 2 * k + 1]);
            else { int k2 = k - 32; v = pack2f(w2h[r * 32 + 2 * k2], w2h[r * 32 + 2 * k2 + 1]); }
            g_w2P[idx] = v;
        }
    } else if (blk == 531) {
        // packed [w1i|w1h] pairs: wc[m] for m<32 -> w1i pair m, m>=32 -> w1h pair m-32
        for (int idx = tid; idx < 16384; idx += 256) {
            int k = idx >> 8, r = idx & 255;
            ull v;
            if (k < 32) v = pack2f(w1i[r * 64 + 2 * k], w1i[r * 64 + 2 * k + 1]);
            else { int k2 = k - 32; v = pack2f(w1h[r * 64 + 2 * k2], w1h[r * 64 + 2 * k2 + 1]); }
            g_wc1P[idx] = v;
        }
    } else if (blk == 532) {
        // packed Wcat2 float k-major: wcat[k] for row g: k<64 -> w2i[g][k], else w2h[g][k-64]
        for (int idx = tid; idx < 12288; idx += 256) {
            int k = idx >> 7, g = idx & 127;
            g_wc2Pf[idx] = (k < 64) ? w2i[g * 64 + k] : w2h[g * 32 + (k - 64)];
        }
    }
}

// ---------------- fused two-layer MLP phase-1 (KA=90, proven 128-row tile) ----------------
__global__ void __launch_bounds__(256) fused_mlp90(
        const float* __restrict__ A,
        const float* __restrict__ W1, const float* __restrict__ b1,
        const float* __restrict__ fc7, float* __restrict__ part) {
    constexpr int KA = 90, KAP = 90, WS = 90, NW = 12;
    extern __shared__ float sm[];
    float* A2 = sm;
    float* W2 = A2 + 128 * KAP;
    float* F2 = W2 + 32 * WS;
    float* Es = F2 + 64 * 36;
    const int tid = threadIdx.x;
    const int s = blockIdx.x, m0 = blockIdx.y * 128;
    for (int idx = tid; idx < 128 * KA; idx += 256) {
        int r = idx / KA, p = idx - r * KA;
        A2[r * KAP + p] = A[(size_t)(m0 + r) * 90 + p];
    }
    ull acc2[8][4];
#pragma unroll
    for (int i = 0; i < 8; i++)
#pragma unroll
        for (int j = 0; j < 4; j++) acc2[i][j] = 0ull;
    const int kbase = s * 256;
    const int txE = tid & 7, tyE = tid >> 3;
    const int txM = tid & 15, tyM = tid >> 4;
    const int eswM = 4 * (tyM & 7);
    const int fswM = 4 * (txM & 7);
    float pw[NW], pf[8];
#pragma unroll
    for (int i = 0; i < NW; i++) {
        int idx = tid + i * 256;
        if (idx < 32 * KA) pw[i] = W1[(size_t)(kbase + idx / KA) * KA + idx % KA];
    }
#pragma unroll
    for (int i = 0; i < 8; i++) {
        int idx = tid + i * 256;
        pf[i] = fc7[(size_t)(idx >> 5) * 4096 + kbase + (idx & 31)];
    }
    for (int kc = 0; kc < 256; kc += 32) {
        const int cg0 = kbase + kc;
        __syncthreads();
#pragma unroll
        for (int i = 0; i < NW; i++) {
            int idx = tid + i * 256;
            if (idx < 32 * KA) W2[(idx / KA) * WS + idx % KA] = pw[i];
        }
#pragma unroll
        for (int i = 0; i < 8; i++) {
            int idx = tid + i * 256;
            int n = idx >> 5, kk = idx & 31;
            F2[n * 36 + (kk ^ (4 * ((n >> 2) & 7)))] = pf[i];
        }
        __syncthreads();
        if (kc + 32 < 256) {
            const int ng0 = cg0 + 32;
#pragma unroll
            for (int i = 0; i < NW; i++) {
                int idx = tid + i * 256;
                if (idx < 32 * KA) pw[i] = W1[(size_t)(ng0 + idx / KA) * KA + idx % KA];
            }
#pragma unroll
            for (int i = 0; i < 8; i++) {
                int idx = tid + i * 256;
                pf[i] = fc7[(size_t)(idx >> 5) * 4096 + ng0 + (idx & 31)];
            }
        }
        ull e2[4][4];
#pragma unroll
        for (int i = 0; i < 4; i++)
#pragma unroll
            for (int j = 0; j < 4; j++) e2[i][j] = 0ull;
#pragma unroll 15
        for (int p = 0; p < KA; p += 2) {
            ull a0 = *(const ull*)&A2[(tyE * 4 + 0) * KAP + p];
            ull a1 = *(const ull*)&A2[(tyE * 4 + 1) * KAP + p];
            ull a2 = *(const ull*)&A2[(tyE * 4 + 2) * KAP + p];
            ull a3 = *(const ull*)&A2[(tyE * 4 + 3) * KAP + p];
            ull w0 = *(const ull*)&W2[(txE * 4 + 0) * WS + p];
            ull w1 = *(const ull*)&W2[(txE * 4 + 1) * WS + p];
            ull w2 = *(const ull*)&W2[(txE * 4 + 2) * WS + p];
            ull w3 = *(const ull*)&W2[(txE * 4 + 3) * WS + p];
            ffma2(e2[0][0], a0, w0); ffma2(e2[0][1], a0, w1);
            ffma2(e2[0][2], a0, w2); ffma2(e2[0][3], a0, w3);
            ffma2(e2[1][0], a1, w0); ffma2(e2[1][1], a1, w1);
            ffma2(e2[1][2], a1, w2); ffma2(e2[1][3], a1, w3);
            ffma2(e2[2][0], a2, w0); ffma2(e2[2][1], a2, w1);
            ffma2(e2[2][2], a2, w2); ffma2(e2[2][3], a2, w3);
            ffma2(e2[3][0], a3, w0); ffma2(e2[3][1], a3, w1);
            ffma2(e2[3][2], a3, w2); ffma2(e2[3][3], a3, w3);
        }
#pragma unroll
        for (int i = 0; i < 4; i++) {
            int r = tyE * 4 + i;
            int swz = 4 * ((r >> 3) & 7);
#pragma unroll
            for (int j = 0; j < 4; j++) {
                int c = txE * 4 + j;
                float2 f = unpack2f(e2[i][j]);
                float v = f.x + f.y + b1[cg0 + c];
                Es[r * 40 + (c ^ swz)] = fmaxf(v, 0.f);
            }
        }
        __syncthreads();
#pragma unroll
        for (int kk = 0; kk < 32; kk += 2) {
            ull e[8], fv[4];
#pragma unroll
            for (int i = 0; i < 8; i++)
                e[i] = *(const ull*)&Es[(tyM * 8 + i) * 40 + (kk ^ eswM)];
#pragma unroll
            for (int j = 0; j < 4; j++)
                fv[j] = *(const ull*)&F2[(txM * 4 + j) * 36 + (kk ^ fswM)];
#pragma unroll
            for (int i = 0; i < 8; i++)
#pragma unroll
                for (int j = 0; j < 4; j++) ffma2(acc2[i][j], e[i], fv[j]);
        }
    }
#pragma unroll
    for (int i = 0; i < 8; i++)
#pragma unroll
        for (int j = 0; j < 4; j++) {
            float2 f = unpack2f(acc2[i][j]);
            part[((size_t)s * NROWS + m0 + tyM * 8 + i) * 64 + txM * 4 + j] = f.x + f.y;
        }
}

// ---------------- reduce partials -> emb, then XP = emb@w1i^T + b1c ----------------
__global__ void __launch_bounds__(256) reduce_xp(const float* __restrict__ fc7_b,
                                                 const float* __restrict__ w1i) {
    extern __shared__ float dsm[];
    float* wS   = dsm;              // [256][66]
    float* embS = dsm + 256 * 66;   // [16][66]
    const int tid = threadIdx.x;
    const int r0 = blockIdx.x * 16;
    {
        int r = tid >> 4, ng = tid & 15;
        float4 acc = *(const float4*)&fc7_b[ng * 4];
#pragma unroll
        for (int ss = 0; ss < SPLITS; ss++) {
            float4 v = *(const float4*)&g_part[((size_t)ss * NROWS + r0 + r) * 64 + ng * 4];
            acc.x += v.x; acc.y += v.y; acc.z += v.z; acc.w += v.w;
        }
        embS[r * 66 + ng * 4 + 0] = fmaxf(acc.x, 0.f);
        embS[r * 66 + ng * 4 + 1] = fmaxf(acc.y, 0.f);
        embS[r * 66 + ng * 4 + 2] = fmaxf(acc.z, 0.f);
        embS[r * 66 + ng * 4 + 3] = fmaxf(acc.w, 0.f);
    }
    for (int idx = tid; idx < 16384; idx += 256)
        wS[(idx >> 6) * 66 + (idx & 63)] = w1i[idx];
    __syncthreads();
    ull w[32];
#pragma unroll
    for (int k = 0; k < 32; k++) w[k] = *(const ull*)&wS[tid * 66 + 2 * k];
    const float bias = g_b1c[tid];
    for (int r = 0; r < 16; r += 2) {
        ull a0 = pack2f(bias, 0.f), a1 = 0ull;
        ull c0 = pack2f(bias, 0.f), c1 = 0ull;
#pragma unroll
        for (int k = 0; k < 16; k++) {
            ffma2(a0, w[2 * k],     *(const ull*)&embS[r * 66 + 4 * k]);
            ffma2(a1, w[2 * k + 1], *(const ull*)&embS[r * 66 + 4 * k + 2]);
            ffma2(c0, w[2 * k],     *(const ull*)&embS[(r + 1) * 66 + 4 * k]);
            ffma2(c1, w[2 * k + 1], *(const ull*)&embS[(r + 1) * 66 + 4 * k + 2]);
        }
        float2 f0 = unpack2f(a0), f1 = unpack2f(a1);
        float2 g0 = unpack2f(c0), g1 = unpack2f(c1);
        g_XP[(size_t)(r0 + r) * 256 + tid]     = (f0.x + f0.y) + (f1.x + f1.y);
        g_XP[(size_t)(r0 + r + 1) * 256 + tid] = (g0.x + g0.y) + (g1.x + g1.y);
    }
}

// ================= PHASE 2: one persistent multi-role kernel =================
// blocks 0-7: scan; 8-263: mlp32 tiles; 264-391: reduce_gates; 392-519: tail
__global__ void __launch_bounds__(384, 1) phase2(
        const float* __restrict__ fc7, const float* __restrict__ fc7_b,
        const float* __restrict__ fc8w, const float* __restrict__ fc8b,
        const float* __restrict__ fw, const float* __restrict__ fb,
        float* __restrict__ out, float* __restrict__ fpooled) {
    extern __shared__ float sm[];
    const int blk = blockIdx.x;
    const int tid = threadIdx.x;

    if (blk < 8) {
        // ---------------- scan role (proven 12-warp design + progress flags) ----------------
        __shared__ __align__(16) float h1s[2][64];
        __shared__ __align__(16) float h2s[2][32];
        const int wid = tid >> 5, lane = tid & 31;
        const int b = blk;
        const float* xp = g_XP + (size_t)b * 65536;
        float* st = g_states + (size_t)b * 49152;
        ull wreg[48];
        float bc2 = 0.f, cst = 0.f;
        const int q = lane & 3;
        int j, r;
        if (wid < 8) {
            j = (wid << 3) + (lane >> 2);
            r = (q << 6) + j;
#pragma unroll
            for (int k = 0; k < 32; k++) wreg[k] = g_w1hP[k * 256 + r];
        } else {
            j = ((wid - 8) << 3) + (lane >> 2);
            r = (q << 5) + j;
#pragma unroll
            for (int k = 0; k < 48; k++) wreg[k] = g_w2P[k * 128 + r];
            bc2 = g_b2c[r];
        }
        if (tid < 64) { h1s[0][tid] = 0.f; h1s[1][tid] = 0.f; }
        if (tid >= 64 && tid < 96) { h2s[0][tid - 64] = 0.f; h2s[1][tid - 64] = 0.f; }
        float xcur = 0.f, x1 = 0.f;
        if (wid < 8) { xcur = xp[r]; x1 = xp[256 + r]; }
        __syncthreads();
        for (int t = 0; t <= 256; t++) {
            if ((t & 31) == 0 && t) {
                __threadfence();
                __syncthreads();
                if (tid == 0) st_rel(&g_prog[b], t - 1);
            }
            const int buf = t & 1;
            if (wid < 8) {
                if (t < 256) {
                    float x2 = 0.f;
                    if (t + 2 < 256) x2 = xp[(t + 2) * 256 + r];
                    const float* hb = h1s[buf];
                    ull a0 = pack2f(xcur, 0.f), a1 = 0ull, a2 = 0ull, a3 = 0ull;
#pragma unroll
                    for (int k = 0; k < 8; k++) {
                        ulonglong2 hA = *(const ulonglong2*)&hb[8 * k + 0];
                        ulonglong2 hB = *(const ulonglong2*)&hb[8 * k + 4];
                        ffma2(a0, wreg[4 * k + 0], hA.x);
                        ffma2(a1, wreg[4 * k + 1], hA.y);
                        ffma2(a2, wreg[4 * k + 2], hB.x);
                        ffma2(a3, wreg[4 * k + 3], hB.y);
                    }
                    float2 f0 = unpack2f(a0), f1 = unpack2f(a1);
                    float2 f2 = unpack2f(a2), f3 = unpack2f(a3);
                    float g = ((f0.x + f0.y) + (f1.x + f1.y)) + ((f2.x + f2.y) + (f3.x + f3.y));
                    float act = (q == 2) ? tanh_f(g) : sig_f(g);
                    const int base = lane & ~3;
                    float fi = __shfl_sync(0xffffffffu, act, base + 0);
                    float ff = __shfl_sync(0xffffffffu, act, base + 1);
                    float fg = __shfl_sync(0xffffffffu, act, base + 2);
                    float fo = __shfl_sync(0xffffffffu, act, base + 3);
                    if (q == 0) {
                        float c = ff * cst + fi * fg;
                        float h = fo * tanh_f(c);
                        cst = c;
                        h1s[buf ^ 1][j] = h;
                        st[t * 192 + j] = h;
                        st[t * 192 + 64 + j] = c;
                    }
                    xcur = x1; x1 = x2;
                }
            } else if (t >= 1) {
                const int tp = t - 1;
                const float* hb1 = h1s[buf];
                const float* hb2 = h2s[buf];
                ull a0 = pack2f(bc2, 0.f), a1 = 0ull, a2 = 0ull, a3 = 0ull;
#pragma unroll
                for (int k = 0; k < 8; k++) {
                    ulonglong2 hA = *(const ulonglong2*)&hb1[8 * k + 0];
                    ulonglong2 hB = *(const ulonglong2*)&hb1[8 * k + 4];
                    ffma2(a0, wreg[4 * k + 0], hA.x);
                    ffma2(a1, wreg[4 * k + 1], hA.y);
                    ffma2(a2, wreg[4 * k + 2], hB.x);
                    ffma2(a3, wreg[4 * k + 3], hB.y);
                }
#pragma unroll
                for (int k = 0; k < 4; k++) {
                    ulonglong2 hA = *(const ulonglong2*)&hb2[8 * k + 0];
                    ulonglong2 hB = *(const ulonglong2*)&hb2[8 * k + 4];
                    ffma2(a0, wreg[32 + 4 * k + 0], hA.x);
                    ffma2(a1, wreg[32 + 4 * k + 1], hA.y);
                    ffma2(a2, wreg[32 + 4 * k + 2], hB.x);
                    ffma2(a3, wreg[32 + 4 * k + 3], hB.y);
                }
                float2 f0 = unpack2f(a0), f1 = unpack2f(a1);
                float2 f2 = unpack2f(a2), f3 = unpack2f(a3);
                float g = ((f0.x + f0.y) + (f1.x + f1.y)) + ((f2.x + f2.y) + (f3.x + f3.y));
                float act = (q == 2) ? tanh_f(g) : sig_f(g);
                const int base = lane & ~3;
                float fi = __shfl_sync(0xffffffffu, act, base + 0);
                float ff = __shfl_sync(0xffffffffu, act, base + 1);
                float fg = __shfl_sync(0xffffffffu, act, base + 2);
                float fo = __shfl_sync(0xffffffffu, act, base + 3);
                if (q == 0) {
                    float c = ff * cst + fi * fg;
                    float h = fo * tanh_f(c);
                    cst = c;
                    h2s[buf ^ 1][j] = h;
                    st[tp * 192 + 128 + j] = h;
                    st[tp * 192 + 160 + j] = c;
                }
            }
            __syncthreads();
        }
        __threadfence();
        __syncthreads();
        if (tid == 0) st_rel(&g_prog[b], 256);
        return;
    }

    if (blk < 264) {
        // ---------------- mlp32 role: fe partials from h2 states ----------------
        constexpr int KA = 32, KAP = 34, WS = 34, NW = 4;
        float* A2 = sm;
        float* W2 = A2 + 128 * KAP;
        float* F2 = W2 + 32 * WS;
        float* Es = F2 + 64 * 36;
        const int idxb = blk - 8;
        const int s = idxb & 15;
        const int u = idxb >> 4;
        const int tile = (u < 8) ? (2 * u) : (2 * (u - 8) + 1);  // first-half tiles first
        const int m0 = tile * 128;
        const int b = m0 >> 8;
        const int needed = (m0 & 255) + 128;
        while (ld_acq(&g_prog[b]) < needed) __nanosleep(256);
        for (int idx = tid; idx < 128 * KA; idx += 384) {
            int rr = idx / KA, p = idx - rr * KA;
            A2[rr * KAP + p] = __ldcg(&g_states[(size_t)(m0 + rr) * 192 + 128 + p]);
        }
        ull acc2[8][4];
#pragma unroll
        for (int i = 0; i < 8; i++)
#pragma unroll
            for (int j = 0; j < 4; j++) acc2[i][j] = 0ull;
        const int kbase = s * 256;
        const int txE = tid & 7, tyE = tid >> 3;
        const int txM = tid & 15, tyM = tid >> 4;
        const int eswM = 4 * (tyM & 7);
        const int fswM = 4 * (txM & 7);
        float pw[NW], pf[8];
        if (tid < 256) {
#pragma unroll
            for (int i = 0; i < NW; i++) {
                int idx = tid + i * 256;
                if (idx < 32 * KA) pw[i] = g_G[(size_t)(kbase + idx / KA) * KA + idx % KA];
            }
#pragma unroll
            for (int i = 0; i < 8; i++) {
                int idx = tid + i * 256;
                pf[i] = fc7[(size_t)(idx >> 5) * 4096 + kbase + (idx & 31)];
            }
        }
        for (int kc = 0; kc < 256; kc += 32) {
            const int cg0 = kbase + kc;
            __syncthreads();
            if (tid < 256) {
#pragma unroll
                for (int i = 0; i < NW; i++) {
                    int idx = tid + i * 256;
                    if (idx < 32 * KA) W2[(idx / KA) * WS + idx % KA] = pw[i];
                }
#pragma unroll
                for (int i = 0; i < 8; i++) {
                    int idx = tid + i * 256;
                    int n = idx >> 5, kk = idx & 31;
                    F2[n * 36 + (kk ^ (4 * ((n >> 2) & 7)))] = pf[i];
                }
            }
            __syncthreads();
            if (tid < 256) {
                if (kc + 32 < 256) {
                    const int ng0 = cg0 + 32;
#pragma unroll
                    for (int i = 0; i < NW; i++) {
                        int idx = tid + i * 256;
                        if (idx < 32 * KA) pw[i] = g_G[(size_t)(ng0 + idx / KA) * KA + idx % KA];
                    }
#pragma unroll
                    for (int i = 0; i < 8; i++) {
                        int idx = tid + i * 256;
                        pf[i] = fc7[(size_t)(idx >> 5) * 4096 + ng0 + (idx & 31)];
                    }
                }
                ull e2[4][4];
#pragma unroll
                for (int i = 0; i < 4; i++)
#pragma unroll
                    for (int j = 0; j < 4; j++) e2[i][j] = 0ull;
#pragma unroll
                for (int p = 0; p < KA; p += 2) {
                    ull a0 = *(const ull*)&A2[(tyE * 4 + 0) * KAP + p];
                    ull a1 = *(const ull*)&A2[(tyE * 4 + 1) * KAP + p];
                    ull a2 = *(const ull*)&A2[(tyE * 4 + 2) * KAP + p];
                    ull a3 = *(const ull*)&A2[(tyE * 4 + 3) * KAP + p];
                    ull w0 = *(const ull*)&W2[(txE * 4 + 0) * WS + p];
                    ull w1 = *(const ull*)&W2[(txE * 4 + 1) * WS + p];
                    ull w2 = *(const ull*)&W2[(txE * 4 + 2) * WS + p];
                    ull w3 = *(const ull*)&W2[(txE * 4 + 3) * WS + p];
                    ffma2(e2[0][0], a0, w0); ffma2(e2[0][1], a0, w1);
                    ffma2(e2[0][2], a0, w2); ffma2(e2[0][3], a0, w3);
                    ffma2(e2[1][0], a1, w0); ffma2(e2[1][1], a1, w1);
                    ffma2(e2[1][2], a1, w2); ffma2(e2[1][3], a1, w3);
                    ffma2(e2[2][0], a2, w0); ffma2(e2[2][1], a2, w1);
                    ffma2(e2[2][2], a2, w2); ffma2(e2[2][3], a2, w3);
                    ffma2(e2[3][0], a3, w0); ffma2(e2[3][1], a3, w1);
                    ffma2(e2[3][2], a3, w2); ffma2(e2[3][3], a3, w3);
                }
#pragma unroll
                for (int i = 0; i < 4; i++) {
                    int rr = tyE * 4 + i;
                    int swz = 4 * ((rr >> 3) & 7);
#pragma unroll
                    for (int j = 0; j < 4; j++) {
                        int c = txE * 4 + j;
                        float2 f = unpack2f(e2[i][j]);
                        float v = f.x + f.y + g_cvec[cg0 + c];
                        Es[rr * 40 + (c ^ swz)] = fmaxf(v, 0.f);
                    }
                }
            }
            __syncthreads();
            if (tid < 256) {
#pragma unroll
                for (int kk = 0; kk < 32; kk += 2) {
                    ull e[8], fv[4];
#pragma unroll
                    for (int i = 0; i < 8; i++)
                        e[i] = *(const ull*)&Es[(tyM * 8 + i) * 40 + (kk ^ eswM)];
#pragma unroll
                    for (int j = 0; j < 4; j++)
                        fv[j] = *(const ull*)&F2[(txM * 4 + j) * 36 + (kk ^ fswM)];
#pragma unroll
                    for (int i = 0; i < 8; i++)
#pragma unroll
                        for (int j = 0; j < 4; j++) ffma2(acc2[i][j], e[i], fv[j]);
                }
            }
        }
        if (tid < 256) {
#pragma unroll
            for (int i = 0; i < 8; i++)
#pragma unroll
                for (int j = 0; j < 4; j++) {
                    float2 f = unpack2f(acc2[i][j]);
                    g_part[((size_t)s * NROWS + m0 + tyM * 8 + i) * 64 + txM * 4 + j] = f.x + f.y;
                }
        }
        __threadfence();
        __syncthreads();
        if (tid == 0) atomicAdd(&g_done32[tile], 1);
        return;
    }

    if (blk < 392) {
        // ---------------- reduce_gates role ----------------
        float* S = sm;   // [16][132]
        const int blk2 = blk - 264;
        const int r0 = blk2 * 16;
        const int tile = blk2 >> 3;
        while (ld_acq(&g_done32[tile]) < 16) __nanosleep(256);
        if (tid < 256) {
            int r = tid >> 4, ng = tid & 15;
            float4 acc = *(const float4*)&fc7_b[ng * 4];
#pragma unroll
            for (int ss = 0; ss < SPLITS; ss++) {
                float4 v = __ldcg((const float4*)&g_part[((size_t)ss * NROWS + r0 + r) * 64 + ng * 4]);
                acc.x += v.x; acc.y += v.y; acc.z += v.z; acc.w += v.w;
            }
            S[r * 132 + ng * 4 + 0] = fmaxf(acc.x, 0.f);
            S[r * 132 + ng * 4 + 1] = fmaxf(acc.y, 0.f);
            S[r * 132 + ng * 4 + 2] = fmaxf(acc.z, 0.f);
            S[r * 132 + ng * 4 + 3] = fmaxf(acc.w, 0.f);
            float4 h = __ldcg((const float4*)&g_states[(size_t)(r0 + r) * 192 + ng * 4]);
            *(float4*)&S[r * 132 + 64 + ng * 4] = h;
        }
        __syncthreads();
        if (tid < 256) {
            ull wc[64];
#pragma unroll
            for (int k = 0; k < 64; k++) wc[k] = g_wc1P[k * 256 + tid];
            const float bias = g_b1c[tid];
            for (int r = 0; r < 16; r += 2) {
                ull a0 = pack2f(bias, 0.f), a1 = 0ull;
                ull c0 = pack2f(bias, 0.f), c1 = 0ull;
#pragma unroll
                for (int k = 0; k < 32; k++) {
                    ffma2(a0, wc[2 * k],     *(const ull*)&S[r * 132 + 4 * k]);
                    ffma2(a1, wc[2 * k + 1], *(const ull*)&S[r * 132 + 4 * k + 2]);
                    ffma2(c0, wc[2 * k],     *(const ull*)&S[(r + 1) * 132 + 4 * k]);
                    ffma2(c1, wc[2 * k + 1], *(const ull*)&S[(r + 1) * 132 + 4 * k + 2]);
                }
                float2 f0 = unpack2f(a0), f1 = unpack2f(a1);
                float2 g0 = unpack2f(c0), g1 = unpack2f(c1);
                g_XP[(size_t)(r0 + r) * 256 + tid]     = (f0.x + f0.y) + (f1.x + f1.y);
                g_XP[(size_t)(r0 + r + 1) * 256 + tid] = (g0.x + g0.y) + (g1.x + g1.y);
            }
        }
        __threadfence();
        __syncthreads();
        if (tid == 0) st_rel(&g_doneRG[blk2], 1);
        return;
    }

    // ---------------- tail role ----------------
    {
        float* fwS = sm;   // [90][34]
        __shared__ float fh1[64], th2s[32], tc2s[32], gs[128];
        const int blk3 = blk - 392;
        const int r0 = blk3 * 16;
        for (int idx = tid; idx < 2880; idx += 384)
            fwS[(idx >> 5) * 34 + (idx & 31)] = fw[idx];
        while (ld_acq(&g_doneRG[blk3]) < 1) __nanosleep(256);
        float wcat[96];
        float fwr[32];
        float b2 = 0.f, w8 = 0.f;
        const int po = tid - 32;
        if (tid < 128) {
#pragma unroll
            for (int k = 0; k < 96; k++) wcat[k] = g_wc2Pf[k * 128 + tid];
            b2 = g_b2c[tid];
            if (tid < 32) w8 = fc8w[tid];
        }
        __syncthreads();
        if (po >= 0 && po < 90) {
#pragma unroll
            for (int k = 0; k < 32; k++) fwr[k] = fwS[po * 34 + k];
        }
        const float b8 = fc8b[0];
        const bool is_tanh2 = (tid >= 64 && tid < 96);
        for (int r = 0; r < 16; r++) {
            const int row = r0 + r;
            const float* xpf = g_XP + (size_t)row * 256;
            const float* st = g_states + (size_t)row * 192;
            if (tid < 64) {
                float i = sig_f(__ldcg(&xpf[tid]));
                float f = sig_f(__ldcg(&xpf[64 + tid]));
                float gg = tanh_f(__ldcg(&xpf[128 + tid]));
                float o = sig_f(__ldcg(&xpf[192 + tid]));
                float cn = f * __ldcg(&st[64 + tid]) + i * gg;
                fh1[tid] = o * tanh_f(cn);
            } else if (tid < 96) {
                th2s[tid - 64] = __ldcg(&st[128 + (tid - 64)]);
            } else if (tid < 128) {
                tc2s[tid - 96] = __ldcg(&st[160 + (tid - 96)]);
            }
            __syncthreads();
            if (tid < 128) {
                float a = b2;
#pragma unroll
                for (int k = 0; k < 64; k++) a += wcat[k] * fh1[k];
#pragma unroll
                for (int k = 0; k < 32; k++) a += wcat[64 + k] * th2s[k];
                gs[tid] = is_tanh2 ? tanh_f(a) : sig_f(a);
            }
            __syncthreads();
            if (tid < 32) {
                float cn = gs[32 + tid] * tc2s[tid] + gs[tid] * gs[64 + tid];
                float fh2 = gs[96 + tid] * tanh_f(cn);
                float v1 = th2s[tid] * w8;
                float v2 = fh2 * w8;
#pragma unroll
                for (int off = 16; off > 0; off >>= 1) {
                    v1 += __shfl_down_sync(0xffffffffu, v1, off);
                    v2 += __shfl_down_sync(0xffffffffu, v2, off);
                }
                if (tid == 0) {
                    out[row] = sig_f(v1 + b8);
                    out[NROWS + row] = sig_f(v2 + b8);
                }
            } else if (po >= 0 && po < 90) {
                float s2 = fb[po];
#pragma unroll
                for (int k = 0; k < 32; k++) s2 += fwr[k] * th2s[k];
                fpooled[(size_t)row * 90 + po] = s2;
            }
            __syncthreads();
        }
    }
}

// ---------------- host ----------------
extern "C" void kernel_launch(void* const* d_in, const int* in_sizes, int n_in,
                              void* d_out, int out_size) {
    const float* frames = (const float*)d_in[0];
    const float* spp_w  = (const float*)d_in[1];
    const float* spp_b  = (const float*)d_in[2];
    const float* fc7_w  = (const float*)d_in[3];
    const float* fc7_b  = (const float*)d_in[4];
    const float* w1i    = (const float*)d_in[5];
    const float* w1h    = (const float*)d_in[6];
    const float* b1i    = (const float*)d_in[7];
    const float* b1h    = (const float*)d_in[8];
    const float* w2i    = (const float*)d_in[9];
    const float* w2h    = (const float*)d_in[10];
    const float* b2i    = (const float*)d_in[11];
    const float* b2h    = (const float*)d_in[12];
    const float* fw     = (const float*)d_in[13];
    const float* fb     = (const float*)d_in[14];
    const float* fc8w   = (const float*)d_in[15];
    const float* fc8b   = (const float*)d_in[16];
    float* out = (float*)d_out;

    float *PART;
    cudaGetSymbolAddress((void**)&PART, g_part);

    const int SM1  = (128 * 90 + 32 * 90 + 64 * 36 + 128 * 40) * 4;
    const int SMRX = (256 * 66 + 16 * 66) * 4;
    const int SMP2 = (128 * 34 + 32 * 34 + 64 * 36 + 128 * 40) * 4;   // 51456 (mlp32 is max role)
    cudaFuncSetAttribute(fused_mlp90, cudaFuncAttributeMaxDynamicSharedMemorySize, SM1);
    cudaFuncSetAttribute(reduce_xp, cudaFuncAttributeMaxDynamicSharedMemorySize, SMRX);
    cudaFuncSetAttribute(phase2, cudaFuncAttributeMaxDynamicSharedMemorySize, SMP2);

    float* pooled  = out + 2 * NROWS;
    float* fpooled = out + 2 * NROWS + NROWS * 90;

    spp_prep<<<6677, 256>>>(frames, pooled, spp_w, spp_b, fw, fb,
                            b1i, b1h, w1i, w1h, w2i, w2h, b2i, b2h);
    fused_mlp90<<<dim3(SPLITS, 16), 256, SM1>>>(pooled, spp_w, spp_b, fc7_w, PART);
    reduce_xp<<<128, 256, SMRX>>>(fc7_b, w1i);
    phase2<<<520, 384, SMP2>>>(fc7_w, fc7_b, fc8w, fc8b, fw, fb, out, fpooled);
}

// round 14
// speedup vs baseline: 1.7037x; 1.1612x over previous
#include <cuda_runtime.h>
#include <cuda_bf16.h>
#include <math.h>

#define NROWS 2048
#define EMBED 4096
#define SPLITS 16

typedef unsigned long long ull;

__device__ __forceinline__ void ffma2(ull& d, ull a, ull b) {
    asm("fma.rn.f32x2 %0, %1, %2, %3;" : "=l"(d) : "l"(a), "l"(b), "l"(d));
}
__device__ __forceinline__ ull pack2f(float x, float y) {
    ull r; asm("mov.b64 %0, {%1, %2};" : "=l"(r) : "f"(x), "f"(y)); return r;
}
__device__ __forceinline__ float2 unpack2f(ull v) {
    float2 f; asm("mov.b64 {%0, %1}, %2;" : "=f"(f.x), "=f"(f.y) : "l"(v)); return f;
}
__device__ __forceinline__ int ld_acq(const int* p) {
    int v; asm volatile("ld.acquire.gpu.global.b32 %0, [%1];" : "=r"(v) : "l"(p)); return v;
}
__device__ __forceinline__ void st_rel(int* p, int v) {
    asm volatile("st.release.gpu.global.b32 [%0], %1;" :: "l"(p), "r"(v));
}

// ---------------- scratch ----------------
__device__ float g_part[SPLITS * NROWS * 64];
__device__ float g_XP[NROWS * 256];
__device__ float g_states[NROWS * 192];
__device__ float g_G[EMBED * 32];
__device__ float g_cvec[EMBED];
__device__ float g_b1c[256];
__device__ float g_b2c[128];
__device__ ull g_w1hP[32 * 256];
__device__ ull g_w2P[48 * 128];
__device__ ull g_wc1P[64 * 256];          // k-major packed [w1i|w1h]
__device__ float g_wc2Pf[96 * 128];
// flags
__device__ int g_prog[8];
__device__ int g_done90[16];
__device__ int g_doneRX[128];
__device__ int g_done32[16];
__device__ int g_doneRG[128];

__device__ __forceinline__ float sig_f(float x) {
    return __fdividef(1.0f, 1.0f + __expf(-x));
}
__device__ __forceinline__ float tanh_f(float x) {
    return __fdividef(2.0f, 1.0f + __expf(-2.0f * x)) - 1.0f;
}

// ---------------- merged SPP + prep ----------------
__global__ void spp_prep(const float* __restrict__ frames, float* __restrict__ pooled,
                         const float* __restrict__ spp_w, const float* __restrict__ spp_b,
                         const float* __restrict__ fw, const float* __restrict__ fb,
                         const float* __restrict__ b1i, const float* __restrict__ b1h,
                         const float* __restrict__ w1i, const float* __restrict__ w1h,
                         const float* __restrict__ w2i, const float* __restrict__ w2h,
                         const float* __restrict__ b2i, const float* __restrict__ b2h) {
    const int tid = threadIdx.x;
    if (blockIdx.x < 6144) {
        __shared__ float tmax[144];
        const int nc = blockIdx.x;
        const int n = nc / 3, c = nc % 3;
        const float* img = frames + (size_t)nc * 9216;
        if (tid < 144) {
            const int ti = tid / 12, tj = tid % 12;
            const float* p = img + ti * 8 * 96 + tj * 8;
            float m = -3.402823466e38f;
#pragma unroll
            for (int r = 0; r < 8; r++) {
                float4 v0 = *(const float4*)(p + r * 96);
                float4 v1 = *(const float4*)(p + r * 96 + 4);
                m = fmaxf(m, fmaxf(fmaxf(v0.x, v0.y), fmaxf(v0.z, v0.w)));
                m = fmaxf(m, fmaxf(fmaxf(v1.x, v1.y), fmaxf(v1.z, v1.w)));
            }
            tmax[tid] = m;
        }
        __syncthreads();
        float* orow = pooled + (size_t)n * 90;
        if (tid < 16) {
            int i = tid / 4, j = tid % 4;
            float m = -3.402823466e38f;
            for (int a = 0; a < 3; a++) for (int b = 0; b < 3; b++)
                m = fmaxf(m, tmax[(i * 3 + a) * 12 + (j * 3 + b)]);
            orow[c * 16 + i * 4 + j] = m;
        } else if (tid < 25) {
            int q = tid - 16, i = q / 3, j = q % 3;
            float m = -3.402823466e38f;
            for (int a = 0; a < 4; a++) for (int b = 0; b < 4; b++)
                m = fmaxf(m, tmax[(i * 4 + a) * 12 + (j * 4 + b)]);
            orow[48 + c * 9 + i * 3 + j] = m;
        } else if (tid < 29) {
            int q = tid - 25, i = q / 2, j = q % 2;
            float m = -3.402823466e38f;
            for (int a = 0; a < 6; a++) for (int b = 0; b < 6; b++)
                m = fmaxf(m, tmax[(i * 6 + a) * 12 + (j * 6 + b)]);
            orow[75 + c * 4 + i * 2 + j] = m;
        } else if (tid == 29) {
            float m = -3.402823466e38f;
            for (int a = 0; a < 144; a++) m = fmaxf(m, tmax[a]);
            orow[87 + c] = m;
        }
        return;
    }
    const int blk = blockIdx.x - 6144;
    if (blk < 512) {
        int o = blk * 256 + tid;
        int i = o >> 5, j = o & 31;
        float s = 0.f;
        for (int p = 0; p < 90; p++) s += spp_w[i * 90 + p] * fw[p * 32 + j];
        g_G[o] = s;
    } else if (blk < 528) {
        int i = (blk - 512) * 256 + tid;
        float s = spp_b[i];
        for (int p = 0; p < 90; p++) s += spp_w[i * 90 + p] * fb[p];
        g_cvec[i] = s;
    } else if (blk == 528) {
        g_b1c[tid] = b1i[tid] + b1h[tid];
        if (tid < 128) g_b2c[tid] = b2i[tid] + b2h[tid];
        if (tid < 8) g_prog[tid] = 0;
        if (tid < 16) { g_done90[tid] = 0; g_done32[tid] = 0; }
        if (tid < 128) { g_doneRX[tid] = 0; g_doneRG[tid] = 0; }
    } else if (blk == 529) {
        for (int idx = tid; idx < 8192; idx += 256) {
            int k = idx >> 8, r = idx & 255;
            g_w1hP[idx] = pack2f(w1h[r * 64 + 2 * k], w1h[r * 64 + 2 * k + 1]);
        }
    } else if (blk == 530) {
        for (int idx = tid; idx < 6144; idx += 256) {
            int k = idx >> 7, r = idx & 127;
            ull v;
            if (k < 32) v = pack2f(w2i[r * 64 + 2 * k], w2i[r * 64 + 2 * k + 1]);
            else { int k2 = k - 32; v = pack2f(w2h[r * 32 + 2 * k2], w2h[r * 32 + 2 * k2 + 1]); }
            g_w2P[idx] = v;
        }
    } else if (blk == 531) {
        for (int idx = tid; idx < 16384; idx += 256) {
            int k = idx >> 8, r = idx & 255;
            ull v;
            if (k < 32) v = pack2f(w1i[r * 64 + 2 * k], w1i[r * 64 + 2 * k + 1]);
            else { int k2 = k - 32; v = pack2f(w1h[r * 64 + 2 * k2], w1h[r * 64 + 2 * k2 + 1]); }
            g_wc1P[idx] = v;
        }
    } else if (blk == 532) {
        for (int idx = tid; idx < 12288; idx += 256) {
            int k = idx >> 7, g = idx & 127;
            g_wc2Pf[idx] = (k < 64) ? w2i[g * 64 + k] : w2h[g * 32 + (k - 64)];
        }
    }
}

// ================= MEGA: everything after SPP in one launch =================
// 0-7 scan | 8-135 mlp90 even | 136-199 rx even | 200-327 mlp90 odd |
// 328-391 rx odd | 392-647 mlp32 | 648-775 RG | 776-903 tail
__global__ void __launch_bounds__(384, 1) mega(
        const float* __restrict__ pooled,
        const float* __restrict__ spp_w, const float* __restrict__ spp_b,
        const float* __restrict__ fc7, const float* __restrict__ fc7_b,
        const float* __restrict__ fc8w, const float* __restrict__ fc8b,
        const float* __restrict__ fw, const float* __restrict__ fb,
        float* __restrict__ out, float* __restrict__ fpooled) {
    extern __shared__ float sm[];
    const int blk = blockIdx.x;
    const int tid = threadIdx.x;

    if (blk < 8) {
        // ---------------- scan role, gated on doneRX chunks ----------------
        __shared__ __align__(16) float h1s[2][64];
        __shared__ __align__(16) float h2s[2][32];
        const int wid = tid >> 5, lane = tid & 31;
        const int b = blk;
        const float* xp = g_XP + (size_t)b * 65536;
        float* st = g_states + (size_t)b * 49152;
        ull wreg[48];
        float bc2 = 0.f, cst = 0.f;
        const int q = lane & 3;
        int j, r;
        if (wid < 8) {
            j = (wid << 3) + (lane >> 2);
            r = (q << 6) + j;
#pragma unroll
            for (int k = 0; k < 32; k++) wreg[k] = g_w1hP[k * 256 + r];
        } else {
            j = ((wid - 8) << 3) + (lane >> 2);
            r = (q << 5) + j;
#pragma unroll
            for (int k = 0; k < 48; k++) wreg[k] = g_w2P[k * 128 + r];
            bc2 = g_b2c[r];
        }
        if (tid < 64) { h1s[0][tid] = 0.f; h1s[1][tid] = 0.f; }
        if (tid >= 64 && tid < 96) { h2s[0][tid - 64] = 0.f; h2s[1][tid - 64] = 0.f; }
        while (ld_acq(&g_doneRX[16 * b]) < 1) __nanosleep(256);
        float xcur = 0.f, x1 = 0.f;
        if (wid < 8) { xcur = __ldcg(&xp[r]); x1 = __ldcg(&xp[256 + r]); }
        __syncthreads();
        for (int t = 0; t <= 256; t++) {
            if ((t & 31) == 0 && t) {
                __threadfence();
                __syncthreads();
                if (tid == 0) st_rel(&g_prog[b], t - 1);
            }
            const int buf = t & 1;
            if (wid < 8) {
                if (t < 256) {
                    float x2 = 0.f;
                    const int row2 = t + 2;
                    if (row2 < 256) {
                        if ((row2 & 15) == 0) {
                            while (ld_acq(&g_doneRX[16 * b + (row2 >> 4)]) < 1) __nanosleep(128);
                        }
                        x2 = __ldcg(&xp[row2 * 256 + r]);
                    }
                    const float* hb = h1s[buf];
                    ull a0 = pack2f(xcur, 0.f), a1 = 0ull, a2 = 0ull, a3 = 0ull;
#pragma unroll
                    for (int k = 0; k < 8; k++) {
                        ulonglong2 hA = *(const ulonglong2*)&hb[8 * k + 0];
                        ulonglong2 hB = *(const ulonglong2*)&hb[8 * k + 4];
                        ffma2(a0, wreg[4 * k + 0], hA.x);
                        ffma2(a1, wreg[4 * k + 1], hA.y);
                        ffma2(a2, wreg[4 * k + 2], hB.x);
                        ffma2(a3, wreg[4 * k + 3], hB.y);
                    }
                    float2 f0 = unpack2f(a0), f1 = unpack2f(a1);
                    float2 f2 = unpack2f(a2), f3 = unpack2f(a3);
                    float g = ((f0.x + f0.y) + (f1.x + f1.y)) + ((f2.x + f2.y) + (f3.x + f3.y));
                    float act = (q == 2) ? tanh_f(g) : sig_f(g);
                    const int base = lane & ~3;
                    float fi = __shfl_sync(0xffffffffu, act, base + 0);
                    float ff = __shfl_sync(0xffffffffu, act, base + 1);
                    float fg = __shfl_sync(0xffffffffu, act, base + 2);
                    float fo = __shfl_sync(0xffffffffu, act, base + 3);
                    if (q == 0) {
                        float c = ff * cst + fi * fg;
                        float h = fo * tanh_f(c);
                        cst = c;
                        h1s[buf ^ 1][j] = h;
                        st[t * 192 + j] = h;
                        st[t * 192 + 64 + j] = c;
                    }
                    xcur = x1; x1 = x2;
                }
            } else if (t >= 1) {
                const int tp = t - 1;
                const float* hb1 = h1s[buf];
                const float* hb2 = h2s[buf];
                ull a0 = pack2f(bc2, 0.f), a1 = 0ull, a2 = 0ull, a3 = 0ull;
#pragma unroll
                for (int k = 0; k < 8; k++) {
                    ulonglong2 hA = *(const ulonglong2*)&hb1[8 * k + 0];
                    ulonglong2 hB = *(const ulonglong2*)&hb1[8 * k + 4];
                    ffma2(a0, wreg[4 * k + 0], hA.x);
                    ffma2(a1, wreg[4 * k + 1], hA.y);
                    ffma2(a2, wreg[4 * k + 2], hB.x);
                    ffma2(a3, wreg[4 * k + 3], hB.y);
                }
#pragma unroll
                for (int k = 0; k < 4; k++) {
                    ulonglong2 hA = *(const ulonglong2*)&hb2[8 * k + 0];
                    ulonglong2 hB = *(const ulonglong2*)&hb2[8 * k + 4];
                    ffma2(a0, wreg[32 + 4 * k + 0], hA.x);
                    ffma2(a1, wreg[32 + 4 * k + 1], hA.y);
                    ffma2(a2, wreg[32 + 4 * k + 2], hB.x);
                    ffma2(a3, wreg[32 + 4 * k + 3], hB.y);
                }
                float2 f0 = unpack2f(a0), f1 = unpack2f(a1);
                float2 f2 = unpack2f(a2), f3 = unpack2f(a3);
                float g = ((f0.x + f0.y) + (f1.x + f1.y)) + ((f2.x + f2.y) + (f3.x + f3.y));
                float act = (q == 2) ? tanh_f(g) : sig_f(g);
                const int base = lane & ~3;
                float fi = __shfl_sync(0xffffffffu, act, base + 0);
                float ff = __shfl_sync(0xffffffffu, act, base + 1);
                float fg = __shfl_sync(0xffffffffu, act, base + 2);
                float fo = __shfl_sync(0xffffffffu, act, base + 3);
                if (q == 0) {
                    float c = ff * cst + fi * fg;
                    float h = fo * tanh_f(c);
                    cst = c;
                    h2s[buf ^ 1][j] = h;
                    st[tp * 192 + 128 + j] = h;
                    st[tp * 192 + 160 + j] = c;
                }
            }
            __syncthreads();
        }
        __threadfence();
        __syncthreads();
        if (tid == 0) st_rel(&g_prog[b], 256);
        return;
    }

    if (blk < 392) {
        const bool is90 = (blk < 136) || (blk >= 200 && blk < 328);
        if (is90) {
            // ---------------- mlp90 role ----------------
            constexpr int KA = 90, KAP = 90, WS = 90, NW = 12;
            float* A2 = sm;
            float* W2 = A2 + 128 * KAP;
            float* F2 = W2 + 32 * WS;
            float* Es = F2 + 64 * 36;
            const int idx0 = (blk < 136) ? (blk - 8) : (blk - 200);
            const int tile = (blk < 136) ? 2 * (idx0 >> 4) : 2 * (idx0 >> 4) + 1;
            const int s = idx0 & 15;
            const int m0 = tile * 128;
            for (int idx = tid; idx < 128 * KA; idx += 384) {
                int rr = idx / KA, p = idx - rr * KA;
                A2[rr * KAP + p] = pooled[(size_t)(m0 + rr) * 90 + p];
            }
            ull acc2[8][4];
#pragma unroll
            for (int i = 0; i < 8; i++)
#pragma unroll
                for (int j = 0; j < 4; j++) acc2[i][j] = 0ull;
            const int kbase = s * 256;
            const int txE = tid & 7, tyE = tid >> 3;
            const int txM = tid & 15, tyM = tid >> 4;
            const int eswM = 4 * (tyM & 7);
            const int fswM = 4 * (txM & 7);
            float pw[NW], pf[8];
            if (tid < 256) {
#pragma unroll
                for (int i = 0; i < NW; i++) {
                    int idx = tid + i * 256;
                    if (idx < 32 * KA) pw[i] = spp_w[(size_t)(kbase + idx / KA) * KA + idx % KA];
                }
#pragma unroll
                for (int i = 0; i < 8; i++) {
                    int idx = tid + i * 256;
                    pf[i] = fc7[(size_t)(idx >> 5) * 4096 + kbase + (idx & 31)];
                }
            }
            for (int kc = 0; kc < 256; kc += 32) {
                const int cg0 = kbase + kc;
                __syncthreads();
                if (tid < 256) {
#pragma unroll
                    for (int i = 0; i < NW; i++) {
                        int idx = tid + i * 256;
                        if (idx < 32 * KA) W2[(idx / KA) * WS + idx % KA] = pw[i];
                    }
#pragma unroll
                    for (int i = 0; i < 8; i++) {
                        int idx = tid + i * 256;
                        int n = idx >> 5, kk = idx & 31;
                        F2[n * 36 + (kk ^ (4 * ((n >> 2) & 7)))] = pf[i];
                    }
                }
                __syncthreads();
                if (tid < 256) {
                    if (kc + 32 < 256) {
                        const int ng0 = cg0 + 32;
#pragma unroll
                        for (int i = 0; i < NW; i++) {
                            int idx = tid + i * 256;
                            if (idx < 32 * KA) pw[i] = spp_w[(size_t)(ng0 + idx / KA) * KA + idx % KA];
                        }
#pragma unroll
                        for (int i = 0; i < 8; i++) {
                            int idx = tid + i * 256;
                            pf[i] = fc7[(size_t)(idx >> 5) * 4096 + ng0 + (idx & 31)];
                        }
                    }
                    ull e2[4][4];
#pragma unroll
                    for (int i = 0; i < 4; i++)
#pragma unroll
                        for (int j = 0; j < 4; j++) e2[i][j] = 0ull;
#pragma unroll 15
                    for (int p = 0; p < KA; p += 2) {
                        ull a0 = *(const ull*)&A2[(tyE * 4 + 0) * KAP + p];
                        ull a1 = *(const ull*)&A2[(tyE * 4 + 1) * KAP + p];
                        ull a2 = *(const ull*)&A2[(tyE * 4 + 2) * KAP + p];
                        ull a3 = *(const ull*)&A2[(tyE * 4 + 3) * KAP + p];
                        ull w0 = *(const ull*)&W2[(txE * 4 + 0) * WS + p];
                        ull w1 = *(const ull*)&W2[(txE * 4 + 1) * WS + p];
                        ull w2 = *(const ull*)&W2[(txE * 4 + 2) * WS + p];
                        ull w3 = *(const ull*)&W2[(txE * 4 + 3) * WS + p];
                        ffma2(e2[0][0], a0, w0); ffma2(e2[0][1], a0, w1);
                        ffma2(e2[0][2], a0, w2); ffma2(e2[0][3], a0, w3);
                        ffma2(e2[1][0], a1, w0); ffma2(e2[1][1], a1, w1);
                        ffma2(e2[1][2], a1, w2); ffma2(e2[1][3], a1, w3);
                        ffma2(e2[2][0], a2, w0); ffma2(e2[2][1], a2, w1);
                        ffma2(e2[2][2], a2, w2); ffma2(e2[2][3], a2, w3);
                        ffma2(e2[3][0], a3, w0); ffma2(e2[3][1], a3, w1);
                        ffma2(e2[3][2], a3, w2); ffma2(e2[3][3], a3, w3);
                    }
#pragma unroll
                    for (int i = 0; i < 4; i++) {
                        int rr = tyE * 4 + i;
                        int swz = 4 * ((rr >> 3) & 7);
#pragma unroll
                        for (int j = 0; j < 4; j++) {
                            int c = txE * 4 + j;
                            float2 f = unpack2f(e2[i][j]);
                            float v = f.x + f.y + spp_b[cg0 + c];
                            Es[rr * 40 + (c ^ swz)] = fmaxf(v, 0.f);
                        }
                    }
                }
                __syncthreads();
                if (tid < 256) {
#pragma unroll
                    for (int kk = 0; kk < 32; kk += 2) {
                        ull e[8], fv[4];
#pragma unroll
                        for (int i = 0; i < 8; i++)
                            e[i] = *(const ull*)&Es[(tyM * 8 + i) * 40 + (kk ^ eswM)];
#pragma unroll
                        for (int j = 0; j < 4; j++)
                            fv[j] = *(const ull*)&F2[(txM * 4 + j) * 36 + (kk ^ fswM)];
#pragma unroll
                        for (int i = 0; i < 8; i++)
#pragma unroll
                            for (int j = 0; j < 4; j++) ffma2(acc2[i][j], e[i], fv[j]);
                    }
                }
            }
            if (tid < 256) {
#pragma unroll
                for (int i = 0; i < 8; i++)
#pragma unroll
                    for (int j = 0; j < 4; j++) {
                        float2 f = unpack2f(acc2[i][j]);
                        g_part[((size_t)s * NROWS + m0 + tyM * 8 + i) * 64 + txM * 4 + j] = f.x + f.y;
                    }
            }
            __threadfence();
            __syncthreads();
            if (tid == 0) atomicAdd(&g_done90[tile], 1);
        } else {
            // ---------------- reduce_xp role (16 rows/chunk) ----------------
            float* embS = sm;   // [16][66]
            const int idx0 = (blk < 200) ? (blk - 136) : (blk - 328);
            const int c = (blk < 200) ? (16 * (idx0 >> 3) + (idx0 & 7))
                                      : (16 * (idx0 >> 3) + 8 + (idx0 & 7));
            const int tile = c >> 3;
            const int r0 = c * 16;
            while (ld_acq(&g_done90[tile]) < 16) __nanosleep(256);
            if (tid < 256) {
                int r = tid >> 4, ng = tid & 15;
                float4 acc = *(const float4*)&fc7_b[ng * 4];
#pragma unroll
                for (int ss = 0; ss < SPLITS; ss++) {
                    float4 v = __ldcg((const float4*)&g_part[((size_t)ss * NROWS + r0 + r) * 64 + ng * 4]);
                    acc.x += v.x; acc.y += v.y; acc.z += v.z; acc.w += v.w;
                }
                embS[r * 66 + ng * 4 + 0] = fmaxf(acc.x, 0.f);
                embS[r * 66 + ng * 4 + 1] = fmaxf(acc.y, 0.f);
                embS[r * 66 + ng * 4 + 2] = fmaxf(acc.z, 0.f);
                embS[r * 66 + ng * 4 + 3] = fmaxf(acc.w, 0.f);
            }
            __syncthreads();
            if (tid < 256) {
                ull w[32];
#pragma unroll
                for (int k = 0; k < 32; k++) w[k] = g_wc1P[k * 256 + tid];
                const float bias = g_b1c[tid];
                for (int r = 0; r < 16; r += 2) {
                    ull a0 = pack2f(bias, 0.f), a1 = 0ull;
                    ull c0 = pack2f(bias, 0.f), c1 = 0ull;
#pragma unroll
                    for (int k = 0; k < 16; k++) {
                        ffma2(a0, w[2 * k],     *(const ull*)&embS[r * 66 + 4 * k]);
                        ffma2(a1, w[2 * k + 1], *(const ull*)&embS[r * 66 + 4 * k + 2]);
                        ffma2(c0, w[2 * k],     *(const ull*)&embS[(r + 1) * 66 + 4 * k]);
                        ffma2(c1, w[2 * k + 1], *(const ull*)&embS[(r + 1) * 66 + 4 * k + 2]);
                    }
                    float2 f0 = unpack2f(a0), f1 = unpack2f(a1);
                    float2 g0 = unpack2f(c0), g1 = unpack2f(c1);
                    g_XP[(size_t)(r0 + r) * 256 + tid]     = (f0.x + f0.y) + (f1.x + f1.y);
                    g_XP[(size_t)(r0 + r + 1) * 256 + tid] = (g0.x + g0.y) + (g1.x + g1.y);
                }
            }
            __threadfence();
            __syncthreads();
            if (tid == 0) st_rel(&g_doneRX[c], 1);
        }
        return;
    }

    if (blk < 648) {
        // ---------------- mlp32 role ----------------
        constexpr int KA = 32, KAP = 34, WS = 34, NW = 4;
        float* A2 = sm;
        float* W2 = A2 + 128 * KAP;
        float* F2 = W2 + 32 * WS;
        float* Es = F2 + 64 * 36;
        const int idxb = blk - 392;
        const int s = idxb & 15;
        const int u = idxb >> 4;
        const int tile = (u < 8) ? (2 * u) : (2 * (u - 8) + 1);
        const int m0 = tile * 128;
        const int b = m0 >> 8;
        const int needed = (m0 & 255) + 128;
        while (ld_acq(&g_prog[b]) < needed) __nanosleep(256);
        for (int idx = tid; idx < 128 * KA; idx += 384) {
            int rr = idx / KA, p = idx - rr * KA;
            A2[rr * KAP + p] = __ldcg(&g_states[(size_t)(m0 + rr) * 192 + 128 + p]);
        }
        ull acc2[8][4];
#pragma unroll
        for (int i = 0; i < 8; i++)
#pragma unroll
            for (int j = 0; j < 4; j++) acc2[i][j] = 0ull;
        const int kbase = s * 256;
        const int txE = tid & 7, tyE = tid >> 3;
        const int txM = tid & 15, tyM = tid >> 4;
        const int eswM = 4 * (tyM & 7);
        const int fswM = 4 * (txM & 7);
        float pw[NW], pf[8];
        if (tid < 256) {
#pragma unroll
            for (int i = 0; i < NW; i++) {
                int idx = tid + i * 256;
                if (idx < 32 * KA) pw[i] = g_G[(size_t)(kbase + idx / KA) * KA + idx % KA];
            }
#pragma unroll
            for (int i = 0; i < 8; i++) {
                int idx = tid + i * 256;
                pf[i] = fc7[(size_t)(idx >> 5) * 4096 + kbase + (idx & 31)];
            }
        }
        for (int kc = 0; kc < 256; kc += 32) {
            const int cg0 = kbase + kc;
            __syncthreads();
            if (tid < 256) {
#pragma unroll
                for (int i = 0; i < NW; i++) {
                    int idx = tid + i * 256;
                    if (idx < 32 * KA) W2[(idx / KA) * WS + idx % KA] = pw[i];
                }
#pragma unroll
                for (int i = 0; i < 8; i++) {
                    int idx = tid + i * 256;
                    int n = idx >> 5, kk = idx & 31;
                    F2[n * 36 + (kk ^ (4 * ((n >> 2) & 7)))] = pf[i];
                }
            }
            __syncthreads();
            if (tid < 256) {
                if (kc + 32 < 256) {
                    const int ng0 = cg0 + 32;
#pragma unroll
                    for (int i = 0; i < NW; i++) {
                        int idx = tid + i * 256;
                        if (idx < 32 * KA) pw[i] = g_G[(size_t)(ng0 + idx / KA) * KA + idx % KA];
                    }
#pragma unroll
                    for (int i = 0; i < 8; i++) {
                        int idx = tid + i * 256;
                        pf[i] = fc7[(size_t)(idx >> 5) * 4096 + ng0 + (idx & 31)];
                    }
                }
                ull e2[4][4];
#pragma unroll
                for (int i = 0; i < 4; i++)
#pragma unroll
                    for (int j = 0; j < 4; j++) e2[i][j] = 0ull;
#pragma unroll
                for (int p = 0; p < KA; p += 2) {
                    ull a0 = *(const ull*)&A2[(tyE * 4 + 0) * KAP + p];
                    ull a1 = *(const ull*)&A2[(tyE * 4 + 1) * KAP + p];
                    ull a2 = *(const ull*)&A2[(tyE * 4 + 2) * KAP + p];
                    ull a3 = *(const ull*)&A2[(tyE * 4 + 3) * KAP + p];
                    ull w0 = *(const ull*)&W2[(txE * 4 + 0) * WS + p];
                    ull w1 = *(const ull*)&W2[(txE * 4 + 1) * WS + p];
                    ull w2 = *(const ull*)&W2[(txE * 4 + 2) * WS + p];
                    ull w3 = *(const ull*)&W2[(txE * 4 + 3) * WS + p];
                    ffma2(e2[0][0], a0, w0); ffma2(e2[0][1], a0, w1);
                    ffma2(e2[0][2], a0, w2); ffma2(e2[0][3], a0, w3);
                    ffma2(e2[1][0], a1, w0); ffma2(e2[1][1], a1, w1);
                    ffma2(e2[1][2], a1, w2); ffma2(e2[1][3], a1, w3);
                    ffma2(e2[2][0], a2, w0); ffma2(e2[2][1], a2, w1);
                    ffma2(e2[2][2], a2, w2); ffma2(e2[2][3], a2, w3);
                    ffma2(e2[3][0], a3, w0); ffma2(e2[3][1], a3, w1);
                    ffma2(e2[3][2], a3, w2); ffma2(e2[3][3], a3, w3);
                }
#pragma unroll
                for (int i = 0; i < 4; i++) {
                    int rr = tyE * 4 + i;
                    int swz = 4 * ((rr >> 3) & 7);
#pragma unroll
                    for (int j = 0; j < 4; j++) {
                        int c = txE * 4 + j;
                        float2 f = unpack2f(e2[i][j]);
                        float v = f.x + f.y + g_cvec[cg0 + c];
                        Es[rr * 40 + (c ^ swz)] = fmaxf(v, 0.f);
                    }
                }
            }
            __syncthreads();
            if (tid < 256) {
#pragma unroll
                for (int kk = 0; kk < 32; kk += 2) {
                    ull e[8], fv[4];
#pragma unroll
                    for (int i = 0; i < 8; i++)
                        e[i] = *(const ull*)&Es[(tyM * 8 + i) * 40 + (kk ^ eswM)];
#pragma unroll
                    for (int j = 0; j < 4; j++)
                        fv[j] = *(const ull*)&F2[(txM * 4 + j) * 36 + (kk ^ fswM)];
#pragma unroll
                    for (int i = 0; i < 8; i++)
#pragma unroll
                        for (int j = 0; j < 4; j++) ffma2(acc2[i][j], e[i], fv[j]);
                }
            }
        }
        if (tid < 256) {
#pragma unroll
            for (int i = 0; i < 8; i++)
#pragma unroll
                for (int j = 0; j < 4; j++) {
                    float2 f = unpack2f(acc2[i][j]);
                    g_part[((size_t)s * NROWS + m0 + tyM * 8 + i) * 64 + txM * 4 + j] = f.x + f.y;
                }
        }
        __threadfence();
        __syncthreads();
        if (tid == 0) atomicAdd(&g_done32[tile], 1);
        return;
    }

    if (blk < 776) {
        // ---------------- reduce_gates role ----------------
        float* S = sm;   // [16][132]
        const int blk2 = blk - 648;
        const int r0 = blk2 * 16;
        const int tile = blk2 >> 3;
        while (ld_acq(&g_done32[tile]) < 16) __nanosleep(256);
        if (tid < 256) {
            int r = tid >> 4, ng = tid & 15;
            float4 acc = *(const float4*)&fc7_b[ng * 4];
#pragma unroll
            for (int ss = 0; ss < SPLITS; ss++) {
                float4 v = __ldcg((const float4*)&g_part[((size_t)ss * NROWS + r0 + r) * 64 + ng * 4]);
                acc.x += v.x; acc.y += v.y; acc.z += v.z; acc.w += v.w;
            }
            S[r * 132 + ng * 4 + 0] = fmaxf(acc.x, 0.f);
            S[r * 132 + ng * 4 + 1] = fmaxf(acc.y, 0.f);
            S[r * 132 + ng * 4 + 2] = fmaxf(acc.z, 0.f);
            S[r * 132 + ng * 4 + 3] = fmaxf(acc.w, 0.f);
            float4 h = __ldcg((const float4*)&g_states[(size_t)(r0 + r) * 192 + ng * 4]);
            *(float4*)&S[r * 132 + 64 + ng * 4] = h;
        }
        __syncthreads();
        if (tid < 256) {
            ull wc[64];
#pragma unroll
            for (int k = 0; k < 64; k++) wc[k] = g_wc1P[k * 256 + tid];
            const float bias = g_b1c[tid];
            for (int r = 0; r < 16; r += 2) {
                ull a0 = pack2f(bias, 0.f), a1 = 0ull;
                ull c0 = pack2f(bias, 0.f), c1 = 0ull;
#pragma unroll
                for (int k = 0; k < 32; k++) {
                    ffma2(a0, wc[2 * k],     *(const ull*)&S[r * 132 + 4 * k]);
                    ffma2(a1, wc[2 * k + 1], *(const ull*)&S[r * 132 + 4 * k + 2]);
                    ffma2(c0, wc[2 * k],     *(const ull*)&S[(r + 1) * 132 + 4 * k]);
                    ffma2(c1, wc[2 * k + 1], *(const ull*)&S[(r + 1) * 132 + 4 * k + 2]);
                }
                float2 f0 = unpack2f(a0), f1 = unpack2f(a1);
                float2 g0 = unpack2f(c0), g1 = unpack2f(c1);
                g_XP[(size_t)(r0 + r) * 256 + tid]     = (f0.x + f0.y) + (f1.x + f1.y);
                g_XP[(size_t)(r0 + r + 1) * 256 + tid] = (g0.x + g0.y) + (g1.x + g1.y);
            }
        }
        __threadfence();
        __syncthreads();
        if (tid == 0) st_rel(&g_doneRG[blk2], 1);
        return;
    }

    // ---------------- tail role ----------------
    {
        float* fwS = sm;   // [90][34]
        __shared__ float fh1[64], th2s[32], tc2s[32], gs[128];
        const int blk3 = blk - 776;
        const int r0 = blk3 * 16;
        for (int idx = tid; idx < 2880; idx += 384)
            fwS[(idx >> 5) * 34 + (idx & 31)] = fw[idx];
        while (ld_acq(&g_doneRG[blk3]) < 1) __nanosleep(256);
        float wcat[96];
        float fwr[32];
        float b2 = 0.f, w8 = 0.f;
        const int po = tid - 32;
        if (tid < 128) {
#pragma unroll
            for (int k = 0; k < 96; k++) wcat[k] = g_wc2Pf[k * 128 + tid];
            b2 = g_b2c[tid];
            if (tid < 32) w8 = fc8w[tid];
        }
        __syncthreads();
        if (po >= 0 && po < 90) {
#pragma unroll
            for (int k = 0; k < 32; k++) fwr[k] = fwS[po * 34 + k];
        }
        const float b8 = fc8b[0];
        const bool is_tanh2 = (tid >= 64 && tid < 96);
        for (int r = 0; r < 16; r++) {
            const int row = r0 + r;
            const float* xpf = g_XP + (size_t)row * 256;
            const float* st = g_states + (size_t)row * 192;
            if (tid < 64) {
                float i = sig_f(__ldcg(&xpf[tid]));
                float f = sig_f(__ldcg(&xpf[64 + tid]));
                float gg = tanh_f(__ldcg(&xpf[128 + tid]));
                float o = sig_f(__ldcg(&xpf[192 + tid]));
                float cn = f * __ldcg(&st[64 + tid]) + i * gg;
                fh1[tid] = o * tanh_f(cn);
            } else if (tid < 96) {
                th2s[tid - 64] = __ldcg(&st[128 + (tid - 64)]);
            } else if (tid < 128) {
                tc2s[tid - 96] = __ldcg(&st[160 + (tid - 96)]);
            }
            __syncthreads();
            if (tid < 128) {
                float a = b2;
#pragma unroll
                for (int k = 0; k < 64; k++) a += wcat[k] * fh1[k];
#pragma unroll
                for (int k = 0; k < 32; k++) a += wcat[64 + k] * th2s[k];
                gs[tid] = is_tanh2 ? tanh_f(a) : sig_f(a);
            }
            __syncthreads();
            if (tid < 32) {
                float cn = gs[32 + tid] * tc2s[tid] + gs[tid] * gs[64 + tid];
                float fh2 = gs[96 + tid] * tanh_f(cn);
                float v1 = th2s[tid] * w8;
                float v2 = fh2 * w8;
#pragma unroll
                for (int off = 16; off > 0; off >>= 1) {
                    v1 += __shfl_down_sync(0xffffffffu, v1, off);
                    v2 += __shfl_down_sync(0xffffffffu, v2, off);
                }
                if (tid == 0) {
                    out[row] = sig_f(v1 + b8);
                    out[NROWS + row] = sig_f(v2 + b8);
                }
            } else if (po >= 0 && po < 90) {
                float s2 = fb[po];
#pragma unroll
                for (int k = 0; k < 32; k++) s2 += fwr[k] * th2s[k];
                fpooled[(size_t)row * 90 + po] = s2;
            }
            __syncthreads();
        }
    }
}

// ---------------- host ----------------
extern "C" void kernel_launch(void* const* d_in, const int* in_sizes, int n_in,
                              void* d_out, int out_size) {
    const float* frames = (const float*)d_in[0];
    const float* spp_w  = (const float*)d_in[1];
    const float* spp_b  = (const float*)d_in[2];
    const float* fc7_w  = (const float*)d_in[3];
    const float* fc7_b  = (const float*)d_in[4];
    const float* w1i    = (const float*)d_in[5];
    const float* w1h    = (const float*)d_in[6];
    const float* b1i    = (const float*)d_in[7];
    const float* b1h    = (const float*)d_in[8];
    const float* w2i    = (const float*)d_in[9];
    const float* w2h    = (const float*)d_in[10];
    const float* b2i    = (const float*)d_in[11];
    const float* b2h    = (const float*)d_in[12];
    const float* fw     = (const float*)d_in[13];
    const float* fb     = (const float*)d_in[14];
    const float* fc8w   = (const float*)d_in[15];
    const float* fc8b   = (const float*)d_in[16];
    float* out = (float*)d_out;

    const int SMM = (128 * 90 + 32 * 90 + 64 * 36 + 128 * 40) * 4;   // 87296 (mlp90 role)
    cudaFuncSetAttribute(mega, cudaFuncAttributeMaxDynamicSharedMemorySize, SMM);

    float* pooled  = out + 2 * NROWS;
    float* fpooled = out + 2 * NROWS + NROWS * 90;

    spp_prep<<<6677, 256>>>(frames, pooled, spp_w, spp_b, fw, fb,
                            b1i, b1h, w1i, w1h, w2i, w2h, b2i, b2h);
    mega<<<904, 384, SMM>>>(pooled, spp_w, spp_b, fc7_w, fc7_b,
                            fc8w, fc8b, fw, fb, out, fpooled);
}